// round 1
// baseline (speedup 1.0000x reference)
#include <cuda_runtime.h>
#include <math.h>

// Problem constants
#define BB   4
#define SS   2048
#define DD   1024
#define HH   16
#define DHH  64
#define MM   (BB*SS)          // 8192 rows

// Scratch (static device globals -- no allocation allowed)
__device__ float g_Q[BB*HH*SS*DHH];     // [b*H+h][s][dh]
__device__ float g_K[BB*HH*SS*DHH];
__device__ float g_V[BB*HH*SS*DHH];
__device__ float g_ctx[MM*DD];          // [b*S+s][H*dh]  (natural for O-proj)

// ---------------------------------------------------------------------------
// SGEMM core: C[128x128] tile = A[M x 1024] * W[1024 x 1024], fp32.
// 256 threads, 8x8 microtile per thread, BK=16, float4 everywhere.
// ---------------------------------------------------------------------------
__device__ __forceinline__ void gemm_core(const float* __restrict__ A,
                                          const float* __restrict__ W,
                                          float acc[8][8])
{
    __shared__ float As[16 * 132];   // transposed A tile, padded
    __shared__ float Bs[16 * 128];   // natural W tile

    const int tid      = threadIdx.x;
    const int blockRow = blockIdx.y * 128;
    const int blockCol = blockIdx.x * 128;
    const int crow     = (tid >> 4) * 8;
    const int ccol     = (tid & 15) * 8;

    for (int kt = 0; kt < 64; kt++) {
        // ---- load tiles ----
        #pragma unroll
        for (int i = 0; i < 2; i++) {
            int idx = tid + i * 256;
            int ar  = idx >> 2;          // 0..127
            int akg = idx & 3;           // 0..3  (k-group of 4)
            float4 av = *(const float4*)&A[(blockRow + ar) * 1024 + kt * 16 + akg * 4];
            As[(akg * 4 + 0) * 132 + ar] = av.x;
            As[(akg * 4 + 1) * 132 + ar] = av.y;
            As[(akg * 4 + 2) * 132 + ar] = av.z;
            As[(akg * 4 + 3) * 132 + ar] = av.w;

            int br  = idx >> 5;          // 0..15
            int bcg = idx & 31;          // 0..31
            *(float4*)&Bs[br * 128 + bcg * 4] =
                *(const float4*)&W[(kt * 16 + br) * 1024 + blockCol + bcg * 4];
        }
        __syncthreads();

        // ---- compute ----
        #pragma unroll
        for (int k = 0; k < 16; k++) {
            float ra[8], rb[8];
            *(float4*)&ra[0] = *(const float4*)&As[k * 132 + crow];
            *(float4*)&ra[4] = *(const float4*)&As[k * 132 + crow + 4];
            *(float4*)&rb[0] = *(const float4*)&Bs[k * 128 + ccol];
            *(float4*)&rb[4] = *(const float4*)&Bs[k * 128 + ccol + 4];
            #pragma unroll
            for (int i = 0; i < 8; i++)
                #pragma unroll
                for (int j = 0; j < 8; j++)
                    acc[i][j] += ra[i] * rb[j];
        }
        __syncthreads();
    }
}

// ---------------------------------------------------------------------------
// QKV projection: grid (8, 64, 3). z selects weight+destination.
// Epilogue scatters into [b*H+h][s][dh] layout.
// ---------------------------------------------------------------------------
__global__ __launch_bounds__(256) void qkv_gemm(const float* __restrict__ X,
                                                const float* __restrict__ Wq,
                                                const float* __restrict__ Wk,
                                                const float* __restrict__ Wv)
{
    float acc[8][8];
    #pragma unroll
    for (int i = 0; i < 8; i++)
        #pragma unroll
        for (int j = 0; j < 8; j++) acc[i][j] = 0.f;

    const float* W   = (blockIdx.z == 0) ? Wq : (blockIdx.z == 1) ? Wk : Wv;
    float*       Out = (blockIdx.z == 0) ? g_Q : (blockIdx.z == 1) ? g_K : g_V;

    gemm_core(X, W, acc);

    const int tid      = threadIdx.x;
    const int blockRow = blockIdx.y * 128;
    const int blockCol = blockIdx.x * 128;
    const int crow     = (tid >> 4) * 8;
    const int ccol     = (tid & 15) * 8;

    #pragma unroll
    for (int i = 0; i < 8; i++) {
        int m = blockRow + crow + i;
        int b = m >> 11;             // /2048
        int s = m & 2047;
        #pragma unroll
        for (int j = 0; j < 8; j += 4) {
            int n = blockCol + ccol + j;
            int h = n >> 6;
            int d = n & 63;
            float4 v = make_float4(acc[i][j], acc[i][j+1], acc[i][j+2], acc[i][j+3]);
            *(float4*)&Out[((b * HH + h) * SS + s) * DHH + d] = v;
        }
    }
}

// ---------------------------------------------------------------------------
// Output projection: Y = g_ctx @ Wo + bo  -> d_out.  grid (8, 64).
// ---------------------------------------------------------------------------
__global__ __launch_bounds__(256) void out_gemm(const float* __restrict__ Wo,
                                                const float* __restrict__ bo,
                                                float* __restrict__ Y)
{
    float acc[8][8];
    #pragma unroll
    for (int i = 0; i < 8; i++)
        #pragma unroll
        for (int j = 0; j < 8; j++) acc[i][j] = 0.f;

    gemm_core(g_ctx, Wo, acc);

    const int tid      = threadIdx.x;
    const int blockRow = blockIdx.y * 128;
    const int blockCol = blockIdx.x * 128;
    const int crow     = (tid >> 4) * 8;
    const int ccol     = (tid & 15) * 8;

    #pragma unroll
    for (int i = 0; i < 8; i++) {
        int m = blockRow + crow + i;
        #pragma unroll
        for (int j = 0; j < 8; j += 4) {
            int n = blockCol + ccol + j;
            float4 bv = *(const float4*)&bo[n];
            float4 v  = make_float4(acc[i][j]   + bv.x, acc[i][j+1] + bv.y,
                                    acc[i][j+2] + bv.z, acc[i][j+3] + bv.w);
            *(float4*)&Y[m * DD + n] = v;
        }
    }
}

// ---------------------------------------------------------------------------
// Causal flash attention, fp32.
// grid (S/64 = 32 q-tiles, B*H = 64). 256 threads = 16(ty) x 16(tx).
// Each thread: 4 q-rows (ty*4..+3) x [4 keys for S | 4 dh-cols for O] (tx*4..+3).
// Q,K stored transposed+XOR-swizzled in smem: inner loop = 2 LDS.128 : 16 FMA.
// P.V uses warp shuffles (p broadcast from the lane that owns that key group).
// ---------------------------------------------------------------------------
__global__ __launch_bounds__(256) void attn_kernel()
{
    __shared__ float Qt[64 * 64];   // [d][row^swz]
    __shared__ float Kt[64 * 64];   // [d][key^swz]
    __shared__ float Vs[64 * 64];   // [key][dh] natural

    const int tid  = threadIdx.x;
    const int ty   = tid >> 4;
    const int tx   = tid & 15;
    const int lane = tid & 31;
    const int bh   = blockIdx.y;    // b*16 + h
    const int qt   = blockIdx.x;

    const float* Qg = g_Q + ((size_t)bh * SS + qt * 64) * DHH;

    // Load Q tile, transposed with XOR swizzle: phys_col = row ^ (4*d4)
    #pragma unroll
    for (int i = 0; i < 4; i++) {
        int idx = tid + i * 256;
        int row = idx >> 4;
        int d4  = idx & 15;
        float4 v = *(const float4*)&Qg[row * 64 + d4 * 4];
        int pc = row ^ (d4 * 4);
        Qt[(d4 * 4 + 0) * 64 + pc] = v.x;
        Qt[(d4 * 4 + 1) * 64 + pc] = v.y;
        Qt[(d4 * 4 + 2) * 64 + pc] = v.z;
        Qt[(d4 * 4 + 3) * 64 + pc] = v.w;
    }

    float m_i[4], l_i[4], o[4][4];
    #pragma unroll
    for (int i = 0; i < 4; i++) {
        m_i[i] = -INFINITY;
        l_i[i] = 0.f;
        #pragma unroll
        for (int j = 0; j < 4; j++) o[i][j] = 0.f;
    }

    for (int kt = 0; kt <= qt; kt++) {
        __syncthreads();   // Qt ready (kt=0) / Vs free from previous P.V

        const float* Kg = g_K + ((size_t)bh * SS + kt * 64) * DHH;
        const float* Vg = g_V + ((size_t)bh * SS + kt * 64) * DHH;
        #pragma unroll
        for (int i = 0; i < 4; i++) {
            int idx = tid + i * 256;
            int row = idx >> 4;
            int d4  = idx & 15;
            float4 kv = *(const float4*)&Kg[row * 64 + d4 * 4];
            int pc = row ^ (d4 * 4);
            Kt[(d4 * 4 + 0) * 64 + pc] = kv.x;
            Kt[(d4 * 4 + 1) * 64 + pc] = kv.y;
            Kt[(d4 * 4 + 2) * 64 + pc] = kv.z;
            Kt[(d4 * 4 + 3) * 64 + pc] = kv.w;
            *(float4*)&Vs[row * 64 + d4 * 4] = *(const float4*)&Vg[row * 64 + d4 * 4];
        }
        __syncthreads();

        // ---- S = Q K^T ----
        float sc[4][4];
        #pragma unroll
        for (int i = 0; i < 4; i++)
            #pragma unroll
            for (int j = 0; j < 4; j++) sc[i][j] = 0.f;

        #pragma unroll
        for (int d4 = 0; d4 < 16; d4++) {
            int qc = (ty * 4) ^ (d4 * 4);
            int kc = (tx * 4) ^ (d4 * 4);
            #pragma unroll
            for (int c = 0; c < 4; c++) {
                int d = d4 * 4 + c;
                float4 qv = *(const float4*)&Qt[d * 64 + qc];
                float4 kv = *(const float4*)&Kt[d * 64 + kc];
                sc[0][0] += qv.x * kv.x; sc[0][1] += qv.x * kv.y; sc[0][2] += qv.x * kv.z; sc[0][3] += qv.x * kv.w;
                sc[1][0] += qv.y * kv.x; sc[1][1] += qv.y * kv.y; sc[1][2] += qv.y * kv.z; sc[1][3] += qv.y * kv.w;
                sc[2][0] += qv.z * kv.x; sc[2][1] += qv.z * kv.y; sc[2][2] += qv.z * kv.z; sc[2][3] += qv.z * kv.w;
                sc[3][0] += qv.w * kv.x; sc[3][1] += qv.w * kv.y; sc[3][2] += qv.w * kv.z; sc[3][3] += qv.w * kv.w;
            }
        }

        // ---- scale + causal mask (only diagonal tile needs masking) ----
        const float scale = 0.03125f;   // 1/sqrt(1024)
        const bool diag = (kt == qt);
        #pragma unroll
        for (int i = 0; i < 4; i++)
            #pragma unroll
            for (int j = 0; j < 4; j++) {
                sc[i][j] *= scale;
                if (diag && (tx * 4 + j) > (ty * 4 + i)) sc[i][j] = -INFINITY;
            }

        // ---- online softmax (row reduction across the 16 tx lanes) ----
        #pragma unroll
        for (int i = 0; i < 4; i++) {
            float mx = fmaxf(fmaxf(sc[i][0], sc[i][1]), fmaxf(sc[i][2], sc[i][3]));
            #pragma unroll
            for (int off = 1; off < 16; off <<= 1)
                mx = fmaxf(mx, __shfl_xor_sync(0xffffffffu, mx, off));
            float mn    = fmaxf(m_i[i], mx);
            float alpha = __expf(m_i[i] - mn);
            m_i[i] = mn;
            float rs = 0.f;
            #pragma unroll
            for (int j = 0; j < 4; j++) {
                float p = __expf(sc[i][j] - mn);
                sc[i][j] = p;
                rs += p;
            }
            #pragma unroll
            for (int off = 1; off < 16; off <<= 1)
                rs += __shfl_xor_sync(0xffffffffu, rs, off);
            l_i[i] = l_i[i] * alpha + rs;
            #pragma unroll
            for (int j = 0; j < 4; j++) o[i][j] *= alpha;
        }

        // ---- O += P V  (p broadcast via shuffle from the lane owning key group) ----
        #pragma unroll
        for (int kg = 0; kg < 16; kg++) {
            int src = (lane & 16) | kg;
            #pragma unroll
            for (int j = 0; j < 4; j++) {
                int key = kg * 4 + j;
                float4 vv = *(const float4*)&Vs[key * 64 + tx * 4];
                #pragma unroll
                for (int i = 0; i < 4; i++) {
                    float pv = __shfl_sync(0xffffffffu, sc[i][j], src);
                    o[i][0] += pv * vv.x;
                    o[i][1] += pv * vv.y;
                    o[i][2] += pv * vv.z;
                    o[i][3] += pv * vv.w;
                }
            }
        }
    }

    // ---- normalize + write ctx in [b*S+s][h*64+dh] layout ----
    const int b = bh >> 4;
    const int h = bh & 15;
    #pragma unroll
    for (int i = 0; i < 4; i++) {
        float inv = 1.f / l_i[i];
        int srow  = qt * 64 + ty * 4 + i;
        float4 v  = make_float4(o[i][0] * inv, o[i][1] * inv, o[i][2] * inv, o[i][3] * inv);
        *(float4*)&g_ctx[((size_t)b * SS + srow) * DD + h * DHH + tx * 4] = v;
    }
}

// ---------------------------------------------------------------------------
extern "C" void kernel_launch(void* const* d_in, const int* in_sizes, int n_in,
                              void* d_out, int out_size)
{
    (void)in_sizes; (void)n_in; (void)out_size;
    const float* X  = (const float*)d_in[0];
    const float* Wq = (const float*)d_in[1];
    const float* Wk = (const float*)d_in[2];
    const float* Wv = (const float*)d_in[3];
    const float* Wo = (const float*)d_in[4];
    const float* bo = (const float*)d_in[5];
    float*       Y  = (float*)d_out;

    dim3 gqkv(DD / 128, MM / 128, 3);      // (8, 64, 3)
    qkv_gemm<<<gqkv, 256>>>(X, Wq, Wk, Wv);

    dim3 gattn(SS / 64, BB * HH);          // (32, 64)
    attn_kernel<<<gattn, 256>>>();

    dim3 go(DD / 128, MM / 128);           // (8, 64)
    out_gemm<<<go, 256>>>(Wo, bo, Y);
}

// round 5
// speedup vs baseline: 1.8006x; 1.8006x over previous
#include <cuda_runtime.h>
#include <math.h>
#include <stdint.h>

// Problem constants
#define BB   4
#define SS   2048
#define DD   1024
#define HH   16
#define DHH  64
#define MM   (BB*SS)          // 8192 rows

// Scratch (static device globals -- no allocation allowed)
__device__ float g_Q[BB*HH*SS*DHH];     // [b*H+h][s][dh]
__device__ float g_K[BB*HH*SS*DHH];
__device__ float g_V[BB*HH*SS*DHH];
__device__ float g_ctx[MM*DD];          // [b*S+s][H*dh]
__device__ float g_Wt[4u*1024u*1024u];  // W^T for q,k,v,o : [n][k], tf32-rounded

// ---------------------------------------------------------------------------
// PTX helpers (baseline sm_100: mma.sync / ldmatrix / cp.async only)
// ---------------------------------------------------------------------------
__device__ __forceinline__ uint32_t smem_u32(const void* p) {
    uint32_t a;
    asm("{ .reg .u64 t; cvta.to.shared.u64 t, %1; cvt.u32.u64 %0, t; }" : "=r"(a) : "l"(p));
    return a;
}

__device__ __forceinline__ float to_tf32(float x) {
    uint32_t u;
    asm("cvt.rna.tf32.f32 %0, %1;" : "=r"(u) : "f"(x));
    return __uint_as_float(u);
}

#define CP_ASYNC16(sa, ga) asm volatile("cp.async.cg.shared.global [%0], [%1], 16;" :: "r"(sa), "l"(ga))
#define CP_COMMIT()        asm volatile("cp.async.commit_group;" ::: "memory")
#define CP_WAIT2()         asm volatile("cp.async.wait_group 2;" ::: "memory")
#define CP_WAIT0()         asm volatile("cp.async.wait_group 0;" ::: "memory")

__device__ __forceinline__ void ldmx4(uint32_t r[4], uint32_t addr) {
    asm volatile("ldmatrix.sync.aligned.m8n8.x4.shared.b16 {%0,%1,%2,%3}, [%4];"
        : "=r"(r[0]), "=r"(r[1]), "=r"(r[2]), "=r"(r[3]) : "r"(addr));
}

__device__ __forceinline__ void mma_tf32(float d[4], const uint32_t a[4],
                                         uint32_t b0, uint32_t b1) {
    asm volatile(
        "mma.sync.aligned.m16n8k8.row.col.f32.tf32.tf32.f32 "
        "{%0,%1,%2,%3}, {%4,%5,%6,%7}, {%8,%9}, {%0,%1,%2,%3};"
        : "+f"(d[0]), "+f"(d[1]), "+f"(d[2]), "+f"(d[3])
        : "r"(a[0]), "r"(a[1]), "r"(a[2]), "r"(a[3]), "r"(b0), "r"(b1));
}

// ---------------------------------------------------------------------------
// W transpose + tf32 rounding: g_Wt[z][n][k] = tf32(W_z[k][n])
// ---------------------------------------------------------------------------
__global__ void transpose_w(const float* __restrict__ W0, const float* __restrict__ W1,
                            const float* __restrict__ W2, const float* __restrict__ W3)
{
    __shared__ float t[32][33];
    const float* W = (blockIdx.z == 0) ? W0 : (blockIdx.z == 1) ? W1 :
                     (blockIdx.z == 2) ? W2 : W3;
    float* O = g_Wt + (size_t)blockIdx.z * 1048576u;
    int tx = threadIdx.x, ty = threadIdx.y;
    int x  = blockIdx.x * 32 + tx;
    int y0 = blockIdx.y * 32;
    #pragma unroll
    for (int j = ty; j < 32; j += 8)
        t[j][tx] = W[(size_t)(y0 + j) * 1024 + x];
    __syncthreads();
    int nx  = blockIdx.y * 32 + tx;
    int ny0 = blockIdx.x * 32;
    #pragma unroll
    for (int j = ty; j < 32; j += 8)
        O[(size_t)(ny0 + j) * 1024 + nx] = to_tf32(t[tx][j]);
}

// ---------------------------------------------------------------------------
// tf32 mma.sync mainloop: acc[128x128 tile] = A[rowblk][1024] * Bt[colblk][1024]^T
// 8 warps (2m x 4n), warp tile 64x32, BK=32, 3-stage cp.async pipeline.
// Smem tiles swizzled: byte = row*128 + ((chunk16 ^ (row&7)) * 16).
// ---------------------------------------------------------------------------
#define STAGE_BYTES 32768u   // A 16KB + B 16KB

__device__ __forceinline__ void mma_mainloop(const float* __restrict__ A,
                                             const float* __restrict__ Bt,
                                             uint32_t sb, float acc[4][4][4])
{
    const int tid  = threadIdx.x;
    const int lane = tid & 31;
    const int wid  = tid >> 5;
    const int wm   = wid >> 2;      // 0..1
    const int wn   = wid & 3;       // 0..3
    const int blockRow = blockIdx.y * 128;
    const int blockCol = blockIdx.x * 128;

    const int crow = tid >> 3;       // 0..31 base rows (x4 unroll -> +32 each)
    const int cchk = tid & 7;        // 16B chunk in row

    // ldmatrix per-lane geometry
    const int r8 = lane & 7;
    const int q  = lane >> 3;        // quadrant group

    // prologue: stages 0,1
    #pragma unroll
    for (int s = 0; s < 2; s++) {
        uint32_t as = sb + (uint32_t)s * STAGE_BYTES;
        uint32_t bs = as + 16384u;
        #pragma unroll
        for (int i = 0; i < 4; i++) {
            int row = crow + i * 32;
            uint32_t sw = (uint32_t)row * 128u + (uint32_t)((cchk ^ (row & 7)) << 4);
            CP_ASYNC16(as + sw, &A [(size_t)(blockRow + row) * 1024 + s * 32 + cchk * 4]);
            CP_ASYNC16(bs + sw, &Bt[(size_t)(blockCol + row) * 1024 + s * 32 + cchk * 4]);
        }
        CP_COMMIT();
    }

    for (int kc = 0; kc < 32; kc++) {
        int nk = kc + 2;
        if (nk < 32) {
            int st = nk % 3;
            uint32_t as = sb + (uint32_t)st * STAGE_BYTES;
            uint32_t bs = as + 16384u;
            #pragma unroll
            for (int i = 0; i < 4; i++) {
                int row = crow + i * 32;
                uint32_t sw = (uint32_t)row * 128u + (uint32_t)((cchk ^ (row & 7)) << 4);
                CP_ASYNC16(as + sw, &A [(size_t)(blockRow + row) * 1024 + nk * 32 + cchk * 4]);
                CP_ASYNC16(bs + sw, &Bt[(size_t)(blockCol + row) * 1024 + nk * 32 + cchk * 4]);
            }
        }
        CP_COMMIT();              // every iter -> group index arithmetic stays exact
        CP_WAIT2();               // stage kc complete
        __syncthreads();

        uint32_t as = sb + (uint32_t)(kc % 3) * STAGE_BYTES;
        uint32_t bs = as + 16384u;

        #pragma unroll
        for (int ks = 0; ks < 4; ks++) {
            uint32_t af[4][4];
            #pragma unroll
            for (int mt = 0; mt < 4; mt++) {
                int row = wm * 64 + mt * 16 + r8 + (q & 1) * 8;
                int ch  = ks * 2 + (q >> 1);
                ldmx4(af[mt], as + (uint32_t)row * 128u + (uint32_t)((ch ^ (row & 7)) << 4));
            }
            uint32_t bf[2][4];
            #pragma unroll
            for (int bp = 0; bp < 2; bp++) {
                int row = wn * 32 + bp * 16 + r8 + (q >> 1) * 8;
                int ch  = ks * 2 + (q & 1);
                ldmx4(bf[bp], bs + (uint32_t)row * 128u + (uint32_t)((ch ^ (row & 7)) << 4));
            }
            #pragma unroll
            for (int mt = 0; mt < 4; mt++)
                #pragma unroll
                for (int nt = 0; nt < 4; nt++)
                    mma_tf32(acc[mt][nt], af[mt],
                             bf[nt >> 1][(nt & 1) * 2], bf[nt >> 1][(nt & 1) * 2 + 1]);
        }
        __syncthreads();
    }
    CP_WAIT0();
}

// ---------------------------------------------------------------------------
// QKV projection (mma.sync tf32): grid (8, 64, 3)
// ---------------------------------------------------------------------------
__global__ __launch_bounds__(256, 2) void qkv_mma(const float* __restrict__ X)
{
    extern __shared__ char dsm[];
    uint32_t sraw = smem_u32(dsm);
    uint32_t sb   = (sraw + 1023u) & ~1023u;

    float acc[4][4][4];
    #pragma unroll
    for (int a = 0; a < 4; a++)
        #pragma unroll
        for (int bq = 0; bq < 4; bq++)
            #pragma unroll
            for (int c = 0; c < 4; c++) acc[a][bq][c] = 0.f;

    const float* Bt  = g_Wt + (size_t)blockIdx.z * 1048576u;
    float*       Out = (blockIdx.z == 0) ? g_Q : (blockIdx.z == 1) ? g_K : g_V;

    mma_mainloop(X, Bt, sb, acc);

    const int lane = threadIdx.x & 31;
    const int wid  = threadIdx.x >> 5;
    const int wm   = wid >> 2, wn = wid & 3;
    const int blockRow = blockIdx.y * 128;
    const int blockCol = blockIdx.x * 128;

    #pragma unroll
    for (int mt = 0; mt < 4; mt++) {
        int m0 = blockRow + wm * 64 + mt * 16 + (lane >> 2);
        #pragma unroll
        for (int half = 0; half < 2; half++) {
            int m = m0 + half * 8;
            int b = m >> 11, s = m & 2047;
            #pragma unroll
            for (int nt = 0; nt < 4; nt++) {
                int n = blockCol + wn * 32 + nt * 8 + (lane & 3) * 2;
                int h = n >> 6, d = n & 63;
                float2 v = make_float2(acc[mt][nt][half * 2], acc[mt][nt][half * 2 + 1]);
                *(float2*)&Out[((size_t)(b * HH + h) * SS + s) * DHH + d] = v;
            }
        }
    }
}

// ---------------------------------------------------------------------------
// Output projection (mma.sync tf32): Y = g_ctx @ Wo + bo.  grid (8, 64)
// ---------------------------------------------------------------------------
__global__ __launch_bounds__(256, 2) void out_mma(const float* __restrict__ bo,
                                                  float* __restrict__ Y)
{
    extern __shared__ char dsm[];
    uint32_t sraw = smem_u32(dsm);
    uint32_t sb   = (sraw + 1023u) & ~1023u;

    float acc[4][4][4];
    #pragma unroll
    for (int a = 0; a < 4; a++)
        #pragma unroll
        for (int bq = 0; bq < 4; bq++)
            #pragma unroll
            for (int c = 0; c < 4; c++) acc[a][bq][c] = 0.f;

    mma_mainloop(g_ctx, g_Wt + 3u * 1048576u, sb, acc);

    const int lane = threadIdx.x & 31;
    const int wid  = threadIdx.x >> 5;
    const int wm   = wid >> 2, wn = wid & 3;
    const int blockRow = blockIdx.y * 128;
    const int blockCol = blockIdx.x * 128;

    #pragma unroll
    for (int mt = 0; mt < 4; mt++) {
        int m0 = blockRow + wm * 64 + mt * 16 + (lane >> 2);
        #pragma unroll
        for (int half = 0; half < 2; half++) {
            int m = m0 + half * 8;
            #pragma unroll
            for (int nt = 0; nt < 4; nt++) {
                int n = blockCol + wn * 32 + nt * 8 + (lane & 3) * 2;
                float2 bv = *(const float2*)&bo[n];
                float2 v  = make_float2(acc[mt][nt][half * 2] + bv.x,
                                        acc[mt][nt][half * 2 + 1] + bv.y);
                *(float2*)&Y[(size_t)m * DD + n] = v;
            }
        }
    }
}

// ---------------------------------------------------------------------------
// Causal flash attention, fp32 (unchanged).
// ---------------------------------------------------------------------------
__global__ __launch_bounds__(256) void attn_kernel()
{
    __shared__ float Qt[64 * 64];
    __shared__ float Kt[64 * 64];
    __shared__ float Vs[64 * 64];

    const int tid  = threadIdx.x;
    const int ty   = tid >> 4;
    const int tx   = tid & 15;
    const int lane = tid & 31;
    const int bh   = blockIdx.y;
    const int qt   = blockIdx.x;

    const float* Qg = g_Q + ((size_t)bh * SS + qt * 64) * DHH;

    #pragma unroll
    for (int i = 0; i < 4; i++) {
        int idx = tid + i * 256;
        int row = idx >> 4;
        int d4  = idx & 15;
        float4 v = *(const float4*)&Qg[row * 64 + d4 * 4];
        int pc = row ^ (d4 * 4);
        Qt[(d4 * 4 + 0) * 64 + pc] = v.x;
        Qt[(d4 * 4 + 1) * 64 + pc] = v.y;
        Qt[(d4 * 4 + 2) * 64 + pc] = v.z;
        Qt[(d4 * 4 + 3) * 64 + pc] = v.w;
    }

    float m_i[4], l_i[4], o[4][4];
    #pragma unroll
    for (int i = 0; i < 4; i++) {
        m_i[i] = -INFINITY;
        l_i[i] = 0.f;
        #pragma unroll
        for (int j = 0; j < 4; j++) o[i][j] = 0.f;
    }

    for (int kt = 0; kt <= qt; kt++) {
        __syncthreads();

        const float* Kg = g_K + ((size_t)bh * SS + kt * 64) * DHH;
        const float* Vg = g_V + ((size_t)bh * SS + kt * 64) * DHH;
        #pragma unroll
        for (int i = 0; i < 4; i++) {
            int idx = tid + i * 256;
            int row = idx >> 4;
            int d4  = idx & 15;
            float4 kv = *(const float4*)&Kg[row * 64 + d4 * 4];
            int pc = row ^ (d4 * 4);
            Kt[(d4 * 4 + 0) * 64 + pc] = kv.x;
            Kt[(d4 * 4 + 1) * 64 + pc] = kv.y;
            Kt[(d4 * 4 + 2) * 64 + pc] = kv.z;
            Kt[(d4 * 4 + 3) * 64 + pc] = kv.w;
            *(float4*)&Vs[row * 64 + d4 * 4] = *(const float4*)&Vg[row * 64 + d4 * 4];
        }
        __syncthreads();

        float sc[4][4];
        #pragma unroll
        for (int i = 0; i < 4; i++)
            #pragma unroll
            for (int j = 0; j < 4; j++) sc[i][j] = 0.f;

        #pragma unroll
        for (int d4 = 0; d4 < 16; d4++) {
            int qc = (ty * 4) ^ (d4 * 4);
            int kc = (tx * 4) ^ (d4 * 4);
            #pragma unroll
            for (int c = 0; c < 4; c++) {
                int d = d4 * 4 + c;
                float4 qv = *(const float4*)&Qt[d * 64 + qc];
                float4 kv = *(const float4*)&Kt[d * 64 + kc];
                sc[0][0] += qv.x * kv.x; sc[0][1] += qv.x * kv.y; sc[0][2] += qv.x * kv.z; sc[0][3] += qv.x * kv.w;
                sc[1][0] += qv.y * kv.x; sc[1][1] += qv.y * kv.y; sc[1][2] += qv.y * kv.z; sc[1][3] += qv.y * kv.w;
                sc[2][0] += qv.z * kv.x; sc[2][1] += qv.z * kv.y; sc[2][2] += qv.z * kv.z; sc[2][3] += qv.z * kv.w;
                sc[3][0] += qv.w * kv.x; sc[3][1] += qv.w * kv.y; sc[3][2] += qv.w * kv.z; sc[3][3] += qv.w * kv.w;
            }
        }

        const float scale = 0.03125f;
        const bool diag = (kt == qt);
        #pragma unroll
        for (int i = 0; i < 4; i++)
            #pragma unroll
            for (int j = 0; j < 4; j++) {
                sc[i][j] *= scale;
                if (diag && (tx * 4 + j) > (ty * 4 + i)) sc[i][j] = -INFINITY;
            }

        #pragma unroll
        for (int i = 0; i < 4; i++) {
            float mx = fmaxf(fmaxf(sc[i][0], sc[i][1]), fmaxf(sc[i][2], sc[i][3]));
            #pragma unroll
            for (int off = 1; off < 16; off <<= 1)
                mx = fmaxf(mx, __shfl_xor_sync(0xffffffffu, mx, off));
            float mn    = fmaxf(m_i[i], mx);
            float alpha = __expf(m_i[i] - mn);
            m_i[i] = mn;
            float rs = 0.f;
            #pragma unroll
            for (int j = 0; j < 4; j++) {
                float p = __expf(sc[i][j] - mn);
                sc[i][j] = p;
                rs += p;
            }
            #pragma unroll
            for (int off = 1; off < 16; off <<= 1)
                rs += __shfl_xor_sync(0xffffffffu, rs, off);
            l_i[i] = l_i[i] * alpha + rs;
            #pragma unroll
            for (int j = 0; j < 4; j++) o[i][j] *= alpha;
        }

        #pragma unroll
        for (int kg = 0; kg < 16; kg++) {
            int src = (lane & 16) | kg;
            #pragma unroll
            for (int j = 0; j < 4; j++) {
                int key = kg * 4 + j;
                float4 vv = *(const float4*)&Vs[key * 64 + tx * 4];
                #pragma unroll
                for (int i = 0; i < 4; i++) {
                    float pv = __shfl_sync(0xffffffffu, sc[i][j], src);
                    o[i][0] += pv * vv.x;
                    o[i][1] += pv * vv.y;
                    o[i][2] += pv * vv.z;
                    o[i][3] += pv * vv.w;
                }
            }
        }
    }

    const int b = bh >> 4;
    const int h = bh & 15;
    #pragma unroll
    for (int i = 0; i < 4; i++) {
        float inv = 1.f / l_i[i];
        int srow  = qt * 64 + ty * 4 + i;
        float4 v  = make_float4(o[i][0] * inv, o[i][1] * inv, o[i][2] * inv, o[i][3] * inv);
        *(float4*)&g_ctx[((size_t)b * SS + srow) * DD + h * DHH + tx * 4] = v;
    }
}

// ---------------------------------------------------------------------------
extern "C" void kernel_launch(void* const* d_in, const int* in_sizes, int n_in,
                              void* d_out, int out_size)
{
    (void)in_sizes; (void)n_in; (void)out_size;
    const float* X  = (const float*)d_in[0];
    const float* Wq = (const float*)d_in[1];
    const float* Wk = (const float*)d_in[2];
    const float* Wv = (const float*)d_in[3];
    const float* Wo = (const float*)d_in[4];
    const float* bo = (const float*)d_in[5];
    float*       Y  = (float*)d_out;

    const int DYN_SMEM = 3 * (int)STAGE_BYTES + 1024;   // 99328
    cudaFuncSetAttribute(qkv_mma, cudaFuncAttributeMaxDynamicSharedMemorySize, DYN_SMEM);
    cudaFuncSetAttribute(out_mma, cudaFuncAttributeMaxDynamicSharedMemorySize, DYN_SMEM);

    dim3 gt(32, 32, 4);
    transpose_w<<<gt, dim3(32, 8)>>>(Wq, Wk, Wv, Wo);

    dim3 gqkv(DD / 128, MM / 128, 3);
    qkv_mma<<<gqkv, 256, DYN_SMEM>>>(X);

    dim3 gattn(SS / 64, BB * HH);
    attn_kernel<<<gattn, 256>>>();

    dim3 go(8, 64);
    out_mma<<<go, 256, DYN_SMEM>>>(bo, Y);
}

// round 10
// speedup vs baseline: 2.6351x; 1.4635x over previous
#include <cuda_runtime.h>
#include <math.h>
#include <stdint.h>

// Problem constants
#define BB   4
#define SS   2048
#define DD   1024
#define HH   16
#define DHH  64
#define MM   (BB*SS)          // 8192 rows

// Scratch (static device globals -- EXACT round-5 set, no additions)
__device__ float g_Q[BB*HH*SS*DHH];     // [b*H+h][s][dh]
__device__ float g_K[BB*HH*SS*DHH];
__device__ float g_V[BB*HH*SS*DHH];
__device__ float g_ctx[MM*DD];          // [b*S+s][H*dh]
__device__ float g_Wt[4u*1024u*1024u];  // W^T for q,k,v,o : [n][k], tf32-rounded

// ---------------------------------------------------------------------------
// PTX helpers (baseline sm_100: mma.sync / ldmatrix / cp.async only)
// ---------------------------------------------------------------------------
__device__ __forceinline__ uint32_t smem_u32(const void* p) {
    uint32_t a;
    asm("{ .reg .u64 t; cvta.to.shared.u64 t, %1; cvt.u32.u64 %0, t; }" : "=r"(a) : "l"(p));
    return a;
}

__device__ __forceinline__ float to_tf32(float x) {
    uint32_t u;
    asm("cvt.rna.tf32.f32 %0, %1;" : "=r"(u) : "f"(x));
    return __uint_as_float(u);
}

#define CP_ASYNC16(sa, ga) asm volatile("cp.async.cg.shared.global [%0], [%1], 16;" :: "r"(sa), "l"(ga))
#define CP_COMMIT()        asm volatile("cp.async.commit_group;" ::: "memory")
#define CP_WAIT2()         asm volatile("cp.async.wait_group 2;" ::: "memory")
#define CP_WAIT0()         asm volatile("cp.async.wait_group 0;" ::: "memory")

__device__ __forceinline__ void ldmx4(uint32_t r[4], uint32_t addr) {
    asm volatile("ldmatrix.sync.aligned.m8n8.x4.shared.b16 {%0,%1,%2,%3}, [%4];"
        : "=r"(r[0]), "=r"(r[1]), "=r"(r[2]), "=r"(r[3]) : "r"(addr));
}

__device__ __forceinline__ void mma_tf32(float d[4], const uint32_t a[4],
                                         uint32_t b0, uint32_t b1) {
    asm volatile(
        "mma.sync.aligned.m16n8k8.row.col.f32.tf32.tf32.f32 "
        "{%0,%1,%2,%3}, {%4,%5,%6,%7}, {%8,%9}, {%0,%1,%2,%3};"
        : "+f"(d[0]), "+f"(d[1]), "+f"(d[2]), "+f"(d[3])
        : "r"(a[0]), "r"(a[1]), "r"(a[2]), "r"(a[3]), "r"(b0), "r"(b1));
}

// ---------------------------------------------------------------------------
// W transpose + tf32 rounding: g_Wt[z][n][k] = tf32(W_z[k][n])  [round-5 exact]
// ---------------------------------------------------------------------------
__global__ void transpose_w(const float* __restrict__ W0, const float* __restrict__ W1,
                            const float* __restrict__ W2, const float* __restrict__ W3)
{
    __shared__ float t[32][33];
    const float* W = (blockIdx.z == 0) ? W0 : (blockIdx.z == 1) ? W1 :
                     (blockIdx.z == 2) ? W2 : W3;
    float* O = g_Wt + (size_t)blockIdx.z * 1048576u;
    int tx = threadIdx.x, ty = threadIdx.y;
    int x  = blockIdx.x * 32 + tx;
    int y0 = blockIdx.y * 32;
    #pragma unroll
    for (int j = ty; j < 32; j += 8)
        t[j][tx] = W[(size_t)(y0 + j) * 1024 + x];
    __syncthreads();
    int nx  = blockIdx.y * 32 + tx;
    int ny0 = blockIdx.x * 32;
    #pragma unroll
    for (int j = ty; j < 32; j += 8)
        O[(size_t)(ny0 + j) * 1024 + nx] = to_tf32(t[tx][j]);
}

// ---------------------------------------------------------------------------
// tf32 mma.sync mainloop  [round-5 exact]
// ---------------------------------------------------------------------------
#define STAGE_BYTES 32768u   // A 16KB + B 16KB

__device__ __forceinline__ void mma_mainloop(const float* __restrict__ A,
                                             const float* __restrict__ Bt,
                                             uint32_t sb, float acc[4][4][4])
{
    const int tid  = threadIdx.x;
    const int lane = tid & 31;
    const int wid  = tid >> 5;
    const int wm   = wid >> 2;
    const int wn   = wid & 3;
    const int blockRow = blockIdx.y * 128;
    const int blockCol = blockIdx.x * 128;

    const int crow = tid >> 3;
    const int cchk = tid & 7;
    const int r8 = lane & 7;
    const int q  = lane >> 3;

    #pragma unroll
    for (int s = 0; s < 2; s++) {
        uint32_t as = sb + (uint32_t)s * STAGE_BYTES;
        uint32_t bs = as + 16384u;
        #pragma unroll
        for (int i = 0; i < 4; i++) {
            int row = crow + i * 32;
            uint32_t sw = (uint32_t)row * 128u + (uint32_t)((cchk ^ (row & 7)) << 4);
            CP_ASYNC16(as + sw, &A [(size_t)(blockRow + row) * 1024 + s * 32 + cchk * 4]);
            CP_ASYNC16(bs + sw, &Bt[(size_t)(blockCol + row) * 1024 + s * 32 + cchk * 4]);
        }
        CP_COMMIT();
    }

    for (int kc = 0; kc < 32; kc++) {
        int nk = kc + 2;
        if (nk < 32) {
            int st = nk % 3;
            uint32_t as = sb + (uint32_t)st * STAGE_BYTES;
            uint32_t bs = as + 16384u;
            #pragma unroll
            for (int i = 0; i < 4; i++) {
                int row = crow + i * 32;
                uint32_t sw = (uint32_t)row * 128u + (uint32_t)((cchk ^ (row & 7)) << 4);
                CP_ASYNC16(as + sw, &A [(size_t)(blockRow + row) * 1024 + nk * 32 + cchk * 4]);
                CP_ASYNC16(bs + sw, &Bt[(size_t)(blockCol + row) * 1024 + nk * 32 + cchk * 4]);
            }
        }
        CP_COMMIT();
        CP_WAIT2();
        __syncthreads();

        uint32_t as = sb + (uint32_t)(kc % 3) * STAGE_BYTES;
        uint32_t bs = as + 16384u;

        #pragma unroll
        for (int ks = 0; ks < 4; ks++) {
            uint32_t af[4][4];
            #pragma unroll
            for (int mt = 0; mt < 4; mt++) {
                int row = wm * 64 + mt * 16 + r8 + (q & 1) * 8;
                int ch  = ks * 2 + (q >> 1);
                ldmx4(af[mt], as + (uint32_t)row * 128u + (uint32_t)((ch ^ (row & 7)) << 4));
            }
            uint32_t bf[2][4];
            #pragma unroll
            for (int bp = 0; bp < 2; bp++) {
                int row = wn * 32 + bp * 16 + r8 + (q >> 1) * 8;
                int ch  = ks * 2 + (q & 1);
                ldmx4(bf[bp], bs + (uint32_t)row * 128u + (uint32_t)((ch ^ (row & 7)) << 4));
            }
            #pragma unroll
            for (int mt = 0; mt < 4; mt++)
                #pragma unroll
                for (int nt = 0; nt < 4; nt++)
                    mma_tf32(acc[mt][nt], af[mt],
                             bf[nt >> 1][(nt & 1) * 2], bf[nt >> 1][(nt & 1) * 2 + 1]);
        }
        __syncthreads();
    }
    CP_WAIT0();
}

// ---------------------------------------------------------------------------
// QKV projection: grid (8, 64, 3)  [round-5 exact]
// ---------------------------------------------------------------------------
__global__ __launch_bounds__(256, 2) void qkv_mma(const float* __restrict__ X)
{
    extern __shared__ char dsm[];
    uint32_t sraw = smem_u32(dsm);
    uint32_t sb   = (sraw + 1023u) & ~1023u;

    float acc[4][4][4];
    #pragma unroll
    for (int a = 0; a < 4; a++)
        #pragma unroll
        for (int bq = 0; bq < 4; bq++)
            #pragma unroll
            for (int c = 0; c < 4; c++) acc[a][bq][c] = 0.f;

    const float* Bt  = g_Wt + (size_t)blockIdx.z * 1048576u;
    float*       Out = (blockIdx.z == 0) ? g_Q : (blockIdx.z == 1) ? g_K : g_V;

    mma_mainloop(X, Bt, sb, acc);

    const int lane = threadIdx.x & 31;
    const int wid  = threadIdx.x >> 5;
    const int wm   = wid >> 2, wn = wid & 3;
    const int blockRow = blockIdx.y * 128;
    const int blockCol = blockIdx.x * 128;

    #pragma unroll
    for (int mt = 0; mt < 4; mt++) {
        int m0 = blockRow + wm * 64 + mt * 16 + (lane >> 2);
        #pragma unroll
        for (int half = 0; half < 2; half++) {
            int m = m0 + half * 8;
            int b = m >> 11, s = m & 2047;
            #pragma unroll
            for (int nt = 0; nt < 4; nt++) {
                int n = blockCol + wn * 32 + nt * 8 + (lane & 3) * 2;
                int h = n >> 6, d = n & 63;
                float2 v = make_float2(acc[mt][nt][half * 2], acc[mt][nt][half * 2 + 1]);
                *(float2*)&Out[((size_t)(b * HH + h) * SS + s) * DHH + d] = v;
            }
        }
    }
}

// ---------------------------------------------------------------------------
// Output projection: Y = g_ctx @ Wo + bo.  grid (8, 64)  [round-5 exact]
// ---------------------------------------------------------------------------
__global__ __launch_bounds__(256, 2) void out_mma(const float* __restrict__ bo,
                                                  float* __restrict__ Y)
{
    extern __shared__ char dsm[];
    uint32_t sraw = smem_u32(dsm);
    uint32_t sb   = (sraw + 1023u) & ~1023u;

    float acc[4][4][4];
    #pragma unroll
    for (int a = 0; a < 4; a++)
        #pragma unroll
        for (int bq = 0; bq < 4; bq++)
            #pragma unroll
            for (int c = 0; c < 4; c++) acc[a][bq][c] = 0.f;

    mma_mainloop(g_ctx, g_Wt + 3u * 1048576u, sb, acc);

    const int lane = threadIdx.x & 31;
    const int wid  = threadIdx.x >> 5;
    const int wm   = wid >> 2, wn = wid & 3;
    const int blockRow = blockIdx.y * 128;
    const int blockCol = blockIdx.x * 128;

    #pragma unroll
    for (int mt = 0; mt < 4; mt++) {
        int m0 = blockRow + wm * 64 + mt * 16 + (lane >> 2);
        #pragma unroll
        for (int half = 0; half < 2; half++) {
            int m = m0 + half * 8;
            #pragma unroll
            for (int nt = 0; nt < 4; nt++) {
                int n = blockCol + wn * 32 + nt * 8 + (lane & 3) * 2;
                float2 bv = *(const float2*)&bo[n];
                float2 v  = make_float2(acc[mt][nt][half * 2] + bv.x,
                                        acc[mt][nt][half * 2 + 1] + bv.y);
                *(float2*)&Y[(size_t)m * DD + n] = v;
            }
        }
    }
}

// ---------------------------------------------------------------------------
// Tensor-core causal flash attention (register-light).
// grid (32 q-tiles, 64 bh), 256 threads = 8 warps as 4(m) x 2(n).
// Br=64, Bc=64. Warp (wm,wn): S-tile 16 q-rows x 32 keys; ctx 16 rows x 32 dh.
// Static smem 48KB: sQ[64x64] | sKP[64x64] (K, then S, then P) | sVt[64x64].
// Softmax: S round-trips through sKP; full row visible to each warp
// (partner lane holds the other half -> one shfl closes row max/sum).
// Swizzle: float4 chunk c of row r lives at chunk (c ^ (r&7)).
// ---------------------------------------------------------------------------
__global__ __launch_bounds__(256) void attn_tc()
{
    __shared__ float sQ[4096];
    __shared__ float sKP[4096];
    __shared__ float sVt[4096];

    const int tid  = threadIdx.x;
    const int lane = tid & 31;
    const int wid  = tid >> 5;
    const int wm   = wid >> 1;          // 0..3 : q-row group
    const int wn   = wid & 1;           // 0..1 : key/dh half
    const int r8   = lane & 7;
    const int q    = lane >> 3;
    const int g    = lane >> 2;         // acc row group
    const int t    = lane & 3;          // acc col pair
    const int bh   = blockIdx.y;
    const int qt   = (gridDim.x - 1) - blockIdx.x;   // heavy tiles first
    const int qbase = qt * 64;

    const float* Qg = g_Q + ((size_t)bh * SS + qbase) * DHH;
    const float* Kg = g_K + (size_t)bh * SS * DHH;
    const float* Vg = g_V + (size_t)bh * SS * DHH;

    const int lr = tid >> 4;   // 0..15
    const int lc = tid & 15;

    const uint32_t sQa = smem_u32(sQ);
    const uint32_t sKPa = smem_u32(sKP);
    const uint32_t sVa = smem_u32(sVt);

    // ---- stage Q tile (RNA-rounded, swizzled) ----
    #pragma unroll
    for (int i = 0; i < 4; i++) {
        int row = lr + i * 16;
        float4 v = *(const float4*)&Qg[(size_t)row * 64 + lc * 4];
        v.x = to_tf32(v.x); v.y = to_tf32(v.y);
        v.z = to_tf32(v.z); v.w = to_tf32(v.w);
        *(float4*)&sQ[row * 64 + ((lc ^ (row & 7)) << 2)] = v;
    }

    float ctx[4][4];
    #pragma unroll
    for (int nt = 0; nt < 4; nt++)
        #pragma unroll
        for (int c = 0; c < 4; c++) ctx[nt][c] = 0.f;
    float m_i[2] = {-INFINITY, -INFINITY};
    float l_i[2] = {0.f, 0.f};

    // row-read-phase geometry: this lane re-reads row rr, chunk half (lane&1)
    const int rrow = wm * 16 + (lane >> 1);          // absolute tile row
    const int rsrcA = ((lane >> 1) & 7) * 4;         // MMA lane owning rr's m_i
    const int mmaA = g * 2;                          // rr-lane holding row g
    const int mmaB = (g + 8) * 2;                    // rr-lane holding row g+8

    for (int kt = 0; kt <= qt; kt++) {
        __syncthreads();   // (A) previous tile fully consumed

        // ---- load K (natural) and V (transposed) tiles, RNA-rounded ----
        const float* Kt = Kg + (size_t)kt * 64 * 64;
        const float* Vt = Vg + (size_t)kt * 64 * 64;
        #pragma unroll
        for (int i = 0; i < 4; i++) {
            int row = lr + i * 16;   // key
            float4 kv = *(const float4*)&Kt[(size_t)row * 64 + lc * 4];
            kv.x = to_tf32(kv.x); kv.y = to_tf32(kv.y);
            kv.z = to_tf32(kv.z); kv.w = to_tf32(kv.w);
            *(float4*)&sKP[row * 64 + ((lc ^ (row & 7)) << 2)] = kv;

            float4 vv = *(const float4*)&Vt[(size_t)row * 64 + lc * 4];
            sVt[(lc * 4 + 0) * 64 + (((row >> 2) ^ ((lc * 4 + 0) & 7)) << 2) + (row & 3)] = to_tf32(vv.x);
            sVt[(lc * 4 + 1) * 64 + (((row >> 2) ^ ((lc * 4 + 1) & 7)) << 2) + (row & 3)] = to_tf32(vv.y);
            sVt[(lc * 4 + 2) * 64 + (((row >> 2) ^ ((lc * 4 + 2) & 7)) << 2) + (row & 3)] = to_tf32(vv.z);
            sVt[(lc * 4 + 3) * 64 + (((row >> 2) ^ ((lc * 4 + 3) & 7)) << 2) + (row & 3)] = to_tf32(vv.w);
        }
        __syncthreads();   // (B) K/V resident

        // ---- S = Q K^T : warp tile 16 x 32 ----
        float sacc[4][4];
        #pragma unroll
        for (int nt = 0; nt < 4; nt++)
            #pragma unroll
            for (int c = 0; c < 4; c++) sacc[nt][c] = 0.f;

        #pragma unroll
        for (int ks = 0; ks < 8; ks++) {
            uint32_t af[4];
            {
                int row = wm * 16 + r8 + (q & 1) * 8;
                int ch  = ks * 2 + (q >> 1);
                ldmx4(af, sQa + (uint32_t)(row * 256 + ((ch ^ (row & 7)) << 4)));
            }
            uint32_t bf[2][4];
            #pragma unroll
            for (int bp = 0; bp < 2; bp++) {
                int row = wn * 32 + bp * 16 + r8 + (q >> 1) * 8;
                int ch  = ks * 2 + (q & 1);
                ldmx4(bf[bp], sKPa + (uint32_t)(row * 256 + ((ch ^ (row & 7)) << 4)));
            }
            #pragma unroll
            for (int nt = 0; nt < 4; nt++)
                mma_tf32(sacc[nt], af,
                         bf[nt >> 1][(nt & 1) * 2], bf[nt >> 1][(nt & 1) * 2 + 1]);
        }
        __syncthreads();   // (C) all K ldmatrix reads done

        // ---- write scaled/masked S into sKP ----
        const float scale = 0.03125f;   // 1/sqrt(1024)
        const bool diag = (kt == qt);
        #pragma unroll
        for (int nt = 0; nt < 4; nt++) {
            #pragma unroll
            for (int r = 0; r < 2; r++) {
                int row = wm * 16 + g + r * 8;
                int col = wn * 32 + nt * 8 + t * 2;
                float v0 = sacc[nt][r * 2]     * scale;
                float v1 = sacc[nt][r * 2 + 1] * scale;
                if (diag) {
                    if (col     > row) v0 = -INFINITY;
                    if (col + 1 > row) v1 = -INFINITY;
                }
                *(float2*)&sKP[row * 64 + (((col >> 2) ^ (row & 7)) << 2) + (col & 3)] =
                    make_float2(v0, v1);
            }
        }
        __syncthreads();   // (D) S fully written

        // ---- full-row read: 8 float4 = half a row per lane ----
        float4 rv[8];
        #pragma unroll
        for (int i = 0; i < 8; i++) {
            int ch2 = (lane & 1) * 8 + i;
            rv[i] = *(const float4*)&sKP[rrow * 64 + ((ch2 ^ (rrow & 7)) << 2)];
        }
        float tmax = -INFINITY;
        #pragma unroll
        for (int i = 0; i < 8; i++)
            tmax = fmaxf(tmax, fmaxf(fmaxf(rv[i].x, rv[i].y), fmaxf(rv[i].z, rv[i].w)));
        tmax = fmaxf(tmax, __shfl_xor_sync(0xffffffffu, tmax, 1));   // full 64-key row

        // old m for this rr-row (fetched from MMA layout)
        float mo0 = __shfl_sync(0xffffffffu, m_i[0], rsrcA);
        float mo1 = __shfl_sync(0xffffffffu, m_i[1], rsrcA);
        float m_old_rr = ((lane >> 1) < 8) ? mo0 : mo1;
        float mnew_rr  = fmaxf(m_old_rr, tmax);

        __syncthreads();   // (E) all reads done; safe to overwrite with P

        // exp + rowsum; write P (RNA) back for own wn half only
        float rsum = 0.f;
        #pragma unroll
        for (int i = 0; i < 8; i++) {
            rv[i].x = __expf(rv[i].x - mnew_rr);
            rv[i].y = __expf(rv[i].y - mnew_rr);
            rv[i].z = __expf(rv[i].z - mnew_rr);
            rv[i].w = __expf(rv[i].w - mnew_rr);
            rsum += rv[i].x + rv[i].y + rv[i].z + rv[i].w;
        }
        rsum += __shfl_xor_sync(0xffffffffu, rsum, 1);               // full-row sum
        if ((lane & 1) == wn) {
            #pragma unroll
            for (int i = 0; i < 8; i++) {
                int ch2 = (lane & 1) * 8 + i;
                float4 pv = make_float4(to_tf32(rv[i].x), to_tf32(rv[i].y),
                                        to_tf32(rv[i].z), to_tf32(rv[i].w));
                *(float4*)&sKP[rrow * 64 + ((ch2 ^ (rrow & 7)) << 2)] = pv;
            }
        }

        // ---- update online stats in MMA layout; rescale ctx ----
        #pragma unroll
        for (int r = 0; r < 2; r++) {
            int src = (r == 0) ? mmaA : mmaB;
            float tm = __shfl_sync(0xffffffffu, tmax, src);
            float rs = __shfl_sync(0xffffffffu, rsum, src);
            float mn = fmaxf(m_i[r], tm);
            float alpha = __expf(m_i[r] - mn);
            m_i[r] = mn;
            l_i[r] = l_i[r] * alpha + rs;
            #pragma unroll
            for (int nt = 0; nt < 4; nt++) {
                ctx[nt][r * 2]     *= alpha;
                ctx[nt][r * 2 + 1] *= alpha;
            }
        }
        __syncthreads();   // (F) P fully written

        // ---- ctx += P V : A = P rows, B = Vt[dh][key] ----
        #pragma unroll
        for (int ks = 0; ks < 8; ks++) {
            uint32_t pf[4];
            {
                int row = wm * 16 + r8 + (q & 1) * 8;
                int ch  = ks * 2 + (q >> 1);
                ldmx4(pf, sKPa + (uint32_t)(row * 256 + ((ch ^ (row & 7)) << 4)));
            }
            uint32_t bf[2][4];
            #pragma unroll
            for (int bp = 0; bp < 2; bp++) {
                int row = wn * 32 + bp * 16 + r8 + (q >> 1) * 8;   // dh
                int ch  = ks * 2 + (q & 1);                        // key chunk
                ldmx4(bf[bp], sVa + (uint32_t)(row * 256 + ((ch ^ (row & 7)) << 4)));
            }
            #pragma unroll
            for (int nt = 0; nt < 4; nt++)
                mma_tf32(ctx[nt], pf,
                         bf[nt >> 1][(nt & 1) * 2], bf[nt >> 1][(nt & 1) * 2 + 1]);
        }
    }

    // ---- normalize + write ctx [b*S+s][h*64+dh] (RNA-rounded) ----
    const int b = bh >> 4;
    const int h = bh & 15;
    #pragma unroll
    for (int r = 0; r < 2; r++) {
        float inv = 1.f / l_i[r];
        int srow  = qbase + wm * 16 + g + r * 8;
        float* dst = &g_ctx[((size_t)b * SS + srow) * DD + h * DHH];
        #pragma unroll
        for (int nt = 0; nt < 4; nt++) {
            int col = wn * 32 + nt * 8 + t * 2;
            float2 v = make_float2(to_tf32(ctx[nt][r * 2] * inv),
                                   to_tf32(ctx[nt][r * 2 + 1] * inv));
            *(float2*)&dst[col] = v;
        }
    }
}

// ---------------------------------------------------------------------------
extern "C" void kernel_launch(void* const* d_in, const int* in_sizes, int n_in,
                              void* d_out, int out_size)
{
    (void)in_sizes; (void)n_in; (void)out_size;
    const float* X  = (const float*)d_in[0];
    const float* Wq = (const float*)d_in[1];
    const float* Wk = (const float*)d_in[2];
    const float* Wv = (const float*)d_in[3];
    const float* Wo = (const float*)d_in[4];
    const float* bo = (const float*)d_in[5];
    float*       Y  = (float*)d_out;

    const int DYN_SMEM = 3 * (int)STAGE_BYTES + 1024;   // 99328
    cudaFuncSetAttribute(qkv_mma, cudaFuncAttributeMaxDynamicSharedMemorySize, DYN_SMEM);
    cudaFuncSetAttribute(out_mma, cudaFuncAttributeMaxDynamicSharedMemorySize, DYN_SMEM);

    dim3 gt(32, 32, 4);
    transpose_w<<<gt, dim3(32, 8)>>>(Wq, Wk, Wv, Wo);

    dim3 gqkv(DD / 128, MM / 128, 3);
    qkv_mma<<<gqkv, 256, DYN_SMEM>>>(X);

    dim3 gattn(SS / 64, BB * HH);
    attn_tc<<<gattn, 256>>>();

    dim3 go(DD / 128, MM / 128);
    out_mma<<<go, 256, DYN_SMEM>>>(bo, Y);
}

// round 11
// speedup vs baseline: 2.6437x; 1.0032x over previous
#include <cuda_runtime.h>
#include <math.h>
#include <stdint.h>

// Problem constants
#define BB   4
#define SS   2048
#define DD   1024
#define HH   16
#define DHH  64
#define MM   (BB*SS)          // 8192 rows

// Scratch (static device globals -- EXACT round-5 set, no additions)
__device__ float g_Q[BB*HH*SS*DHH];     // [b*H+h][s][dh]
__device__ float g_K[BB*HH*SS*DHH];
__device__ float g_V[BB*HH*SS*DHH];
__device__ float g_ctx[MM*DD];          // [b*S+s][H*dh]
__device__ float g_Wt[4u*1024u*1024u];  // W^T for q,k,v,o : [n][k], tf32-rounded

// ---------------------------------------------------------------------------
// PTX helpers (baseline sm_100: mma.sync / ldmatrix / cp.async only)
// ---------------------------------------------------------------------------
__device__ __forceinline__ uint32_t smem_u32(const void* p) {
    uint32_t a;
    asm("{ .reg .u64 t; cvta.to.shared.u64 t, %1; cvt.u32.u64 %0, t; }" : "=r"(a) : "l"(p));
    return a;
}

__device__ __forceinline__ float to_tf32(float x) {
    uint32_t u;
    asm("cvt.rna.tf32.f32 %0, %1;" : "=r"(u) : "f"(x));
    return __uint_as_float(u);
}

#define CP_ASYNC16(sa, ga) asm volatile("cp.async.cg.shared.global [%0], [%1], 16;" :: "r"(sa), "l"(ga))
#define CP_COMMIT()        asm volatile("cp.async.commit_group;" ::: "memory")
#define CP_WAIT2()         asm volatile("cp.async.wait_group 2;" ::: "memory")
#define CP_WAIT0()         asm volatile("cp.async.wait_group 0;" ::: "memory")

__device__ __forceinline__ void ldmx4(uint32_t r[4], uint32_t addr) {
    asm volatile("ldmatrix.sync.aligned.m8n8.x4.shared.b16 {%0,%1,%2,%3}, [%4];"
        : "=r"(r[0]), "=r"(r[1]), "=r"(r[2]), "=r"(r[3]) : "r"(addr));
}

__device__ __forceinline__ void mma_tf32(float d[4], const uint32_t a[4],
                                         uint32_t b0, uint32_t b1) {
    asm volatile(
        "mma.sync.aligned.m16n8k8.row.col.f32.tf32.tf32.f32 "
        "{%0,%1,%2,%3}, {%4,%5,%6,%7}, {%8,%9}, {%0,%1,%2,%3};"
        : "+f"(d[0]), "+f"(d[1]), "+f"(d[2]), "+f"(d[3])
        : "r"(a[0]), "r"(a[1]), "r"(a[2]), "r"(a[3]), "r"(b0), "r"(b1));
}

// ---------------------------------------------------------------------------
// W transpose + tf32 rounding: g_Wt[z][n][k] = tf32(W_z[k][n])  [round-5 exact]
// ---------------------------------------------------------------------------
__global__ void transpose_w(const float* __restrict__ W0, const float* __restrict__ W1,
                            const float* __restrict__ W2, const float* __restrict__ W3)
{
    __shared__ float t[32][33];
    const float* W = (blockIdx.z == 0) ? W0 : (blockIdx.z == 1) ? W1 :
                     (blockIdx.z == 2) ? W2 : W3;
    float* O = g_Wt + (size_t)blockIdx.z * 1048576u;
    int tx = threadIdx.x, ty = threadIdx.y;
    int x  = blockIdx.x * 32 + tx;
    int y0 = blockIdx.y * 32;
    #pragma unroll
    for (int j = ty; j < 32; j += 8)
        t[j][tx] = W[(size_t)(y0 + j) * 1024 + x];
    __syncthreads();
    int nx  = blockIdx.y * 32 + tx;
    int ny0 = blockIdx.x * 32;
    #pragma unroll
    for (int j = ty; j < 32; j += 8)
        O[(size_t)(ny0 + j) * 1024 + nx] = to_tf32(t[tx][j]);
}

// ---------------------------------------------------------------------------
// tf32 mma.sync mainloop  [round-5 exact]
// ---------------------------------------------------------------------------
#define STAGE_BYTES 32768u   // A 16KB + B 16KB

__device__ __forceinline__ void mma_mainloop(const float* __restrict__ A,
                                             const float* __restrict__ Bt,
                                             uint32_t sb, float acc[4][4][4])
{
    const int tid  = threadIdx.x;
    const int lane = tid & 31;
    const int wid  = tid >> 5;
    const int wm   = wid >> 2;
    const int wn   = wid & 3;
    const int blockRow = blockIdx.y * 128;
    const int blockCol = blockIdx.x * 128;

    const int crow = tid >> 3;
    const int cchk = tid & 7;
    const int r8 = lane & 7;
    const int q  = lane >> 3;

    #pragma unroll
    for (int s = 0; s < 2; s++) {
        uint32_t as = sb + (uint32_t)s * STAGE_BYTES;
        uint32_t bs = as + 16384u;
        #pragma unroll
        for (int i = 0; i < 4; i++) {
            int row = crow + i * 32;
            uint32_t sw = (uint32_t)row * 128u + (uint32_t)((cchk ^ (row & 7)) << 4);
            CP_ASYNC16(as + sw, &A [(size_t)(blockRow + row) * 1024 + s * 32 + cchk * 4]);
            CP_ASYNC16(bs + sw, &Bt[(size_t)(blockCol + row) * 1024 + s * 32 + cchk * 4]);
        }
        CP_COMMIT();
    }

    for (int kc = 0; kc < 32; kc++) {
        int nk = kc + 2;
        if (nk < 32) {
            int st = nk % 3;
            uint32_t as = sb + (uint32_t)st * STAGE_BYTES;
            uint32_t bs = as + 16384u;
            #pragma unroll
            for (int i = 0; i < 4; i++) {
                int row = crow + i * 32;
                uint32_t sw = (uint32_t)row * 128u + (uint32_t)((cchk ^ (row & 7)) << 4);
                CP_ASYNC16(as + sw, &A [(size_t)(blockRow + row) * 1024 + nk * 32 + cchk * 4]);
                CP_ASYNC16(bs + sw, &Bt[(size_t)(blockCol + row) * 1024 + nk * 32 + cchk * 4]);
            }
        }
        CP_COMMIT();
        CP_WAIT2();
        __syncthreads();

        uint32_t as = sb + (uint32_t)(kc % 3) * STAGE_BYTES;
        uint32_t bs = as + 16384u;

        #pragma unroll
        for (int ks = 0; ks < 4; ks++) {
            uint32_t af[4][4];
            #pragma unroll
            for (int mt = 0; mt < 4; mt++) {
                int row = wm * 64 + mt * 16 + r8 + (q & 1) * 8;
                int ch  = ks * 2 + (q >> 1);
                ldmx4(af[mt], as + (uint32_t)row * 128u + (uint32_t)((ch ^ (row & 7)) << 4));
            }
            uint32_t bf[2][4];
            #pragma unroll
            for (int bp = 0; bp < 2; bp++) {
                int row = wn * 32 + bp * 16 + r8 + (q >> 1) * 8;
                int ch  = ks * 2 + (q & 1);
                ldmx4(bf[bp], bs + (uint32_t)row * 128u + (uint32_t)((ch ^ (row & 7)) << 4));
            }
            #pragma unroll
            for (int mt = 0; mt < 4; mt++)
                #pragma unroll
                for (int nt = 0; nt < 4; nt++)
                    mma_tf32(acc[mt][nt], af[mt],
                             bf[nt >> 1][(nt & 1) * 2], bf[nt >> 1][(nt & 1) * 2 + 1]);
        }
        __syncthreads();
    }
    CP_WAIT0();
}

// ---------------------------------------------------------------------------
// QKV projection: grid (8, 64, 3)  [round-5 exact]
// ---------------------------------------------------------------------------
__global__ __launch_bounds__(256, 2) void qkv_mma(const float* __restrict__ X)
{
    extern __shared__ char dsm[];
    uint32_t sraw = smem_u32(dsm);
    uint32_t sb   = (sraw + 1023u) & ~1023u;

    float acc[4][4][4];
    #pragma unroll
    for (int a = 0; a < 4; a++)
        #pragma unroll
        for (int bq = 0; bq < 4; bq++)
            #pragma unroll
            for (int c = 0; c < 4; c++) acc[a][bq][c] = 0.f;

    const float* Bt  = g_Wt + (size_t)blockIdx.z * 1048576u;
    float*       Out = (blockIdx.z == 0) ? g_Q : (blockIdx.z == 1) ? g_K : g_V;

    mma_mainloop(X, Bt, sb, acc);

    const int lane = threadIdx.x & 31;
    const int wid  = threadIdx.x >> 5;
    const int wm   = wid >> 2, wn = wid & 3;
    const int blockRow = blockIdx.y * 128;
    const int blockCol = blockIdx.x * 128;

    #pragma unroll
    for (int mt = 0; mt < 4; mt++) {
        int m0 = blockRow + wm * 64 + mt * 16 + (lane >> 2);
        #pragma unroll
        for (int half = 0; half < 2; half++) {
            int m = m0 + half * 8;
            int b = m >> 11, s = m & 2047;
            #pragma unroll
            for (int nt = 0; nt < 4; nt++) {
                int n = blockCol + wn * 32 + nt * 8 + (lane & 3) * 2;
                int h = n >> 6, d = n & 63;
                float2 v = make_float2(acc[mt][nt][half * 2], acc[mt][nt][half * 2 + 1]);
                *(float2*)&Out[((size_t)(b * HH + h) * SS + s) * DHH + d] = v;
            }
        }
    }
}

// ---------------------------------------------------------------------------
// Output projection: Y = g_ctx @ Wo + bo.  grid (8, 64)  [round-5 exact]
// ---------------------------------------------------------------------------
__global__ __launch_bounds__(256, 2) void out_mma(const float* __restrict__ bo,
                                                  float* __restrict__ Y)
{
    extern __shared__ char dsm[];
    uint32_t sraw = smem_u32(dsm);
    uint32_t sb   = (sraw + 1023u) & ~1023u;

    float acc[4][4][4];
    #pragma unroll
    for (int a = 0; a < 4; a++)
        #pragma unroll
        for (int bq = 0; bq < 4; bq++)
            #pragma unroll
            for (int c = 0; c < 4; c++) acc[a][bq][c] = 0.f;

    mma_mainloop(g_ctx, g_Wt + 3u * 1048576u, sb, acc);

    const int lane = threadIdx.x & 31;
    const int wid  = threadIdx.x >> 5;
    const int wm   = wid >> 2, wn = wid & 3;
    const int blockRow = blockIdx.y * 128;
    const int blockCol = blockIdx.x * 128;

    #pragma unroll
    for (int mt = 0; mt < 4; mt++) {
        int m0 = blockRow + wm * 64 + mt * 16 + (lane >> 2);
        #pragma unroll
        for (int half = 0; half < 2; half++) {
            int m = m0 + half * 8;
            #pragma unroll
            for (int nt = 0; nt < 4; nt++) {
                int n = blockCol + wn * 32 + nt * 8 + (lane & 3) * 2;
                float2 bv = *(const float2*)&bo[n];
                float2 v  = make_float2(acc[mt][nt][half * 2] + bv.x,
                                        acc[mt][nt][half * 2 + 1] + bv.y);
                *(float2*)&Y[(size_t)m * DD + n] = v;
            }
        }
    }
}

// ---------------------------------------------------------------------------
// Tensor-core causal flash attention (register-light, pipelined).
// grid (32 q-tiles, 64 bh), 256 threads = 8 warps as 4(m) x 2(n).
// Same structure as the round-10 pass, plus:
//   - K/V register prefetch (next tile's LDGs overlap with MMA/softmax)
//   - improved sVt swizzle f(dh)=(dh+(dh>>3))&7 -> V scatter 2-way (was 8-way)
// Static smem 48KB: sQ[64x64] | sKP[64x64] (K -> S -> P) | sVt[64x64].
// ---------------------------------------------------------------------------
__global__ __launch_bounds__(256) void attn_tc()
{
    __shared__ float sQ[4096];
    __shared__ float sKP[4096];
    __shared__ float sVt[4096];

    const int tid  = threadIdx.x;
    const int lane = tid & 31;
    const int wid  = tid >> 5;
    const int wm   = wid >> 1;          // 0..3 : q-row group
    const int wn   = wid & 1;           // 0..1 : key/dh half
    const int r8   = lane & 7;
    const int q    = lane >> 3;
    const int g    = lane >> 2;         // acc row group
    const int t    = lane & 3;          // acc col pair
    const int bh   = blockIdx.y;
    const int qt   = (gridDim.x - 1) - blockIdx.x;   // heavy tiles first
    const int qbase = qt * 64;

    const float* Qg = g_Q + ((size_t)bh * SS + qbase) * DHH;
    const float* Kg = g_K + (size_t)bh * SS * DHH;
    const float* Vg = g_V + (size_t)bh * SS * DHH;

    const int lr = tid >> 4;   // 0..15
    const int lc = tid & 15;

    const uint32_t sQa = smem_u32(sQ);
    const uint32_t sKPa = smem_u32(sKP);
    const uint32_t sVa = smem_u32(sVt);

    // ---- stage Q tile (RNA-rounded, swizzled) ----
    #pragma unroll
    for (int i = 0; i < 4; i++) {
        int row = lr + i * 16;
        float4 v = *(const float4*)&Qg[(size_t)row * 64 + lc * 4];
        v.x = to_tf32(v.x); v.y = to_tf32(v.y);
        v.z = to_tf32(v.z); v.w = to_tf32(v.w);
        *(float4*)&sQ[row * 64 + ((lc ^ (row & 7)) << 2)] = v;
    }

    float ctx[4][4];
    #pragma unroll
    for (int nt = 0; nt < 4; nt++)
        #pragma unroll
        for (int c = 0; c < 4; c++) ctx[nt][c] = 0.f;
    float m_i[2] = {-INFINITY, -INFINITY};
    float l_i[2] = {0.f, 0.f};

    // row-read-phase geometry
    const int rrow = wm * 16 + (lane >> 1);
    const int rsrcA = ((lane >> 1) & 7) * 4;
    const int mmaA = g * 2;
    const int mmaB = (g + 8) * 2;

    // ---- prologue: prefetch tile 0 into registers ----
    float4 kreg[4], vreg[4];
    #pragma unroll
    for (int i = 0; i < 4; i++) {
        int row = lr + i * 16;
        kreg[i] = *(const float4*)&Kg[(size_t)row * 64 + lc * 4];
        vreg[i] = *(const float4*)&Vg[(size_t)row * 64 + lc * 4];
    }

    for (int kt = 0; kt <= qt; kt++) {
        __syncthreads();   // (A) previous tile fully consumed

        // ---- store prefetched K (natural) and V (transposed), RNA-rounded ----
        #pragma unroll
        for (int i = 0; i < 4; i++) {
            int row = lr + i * 16;   // key
            float4 kv = kreg[i];
            kv.x = to_tf32(kv.x); kv.y = to_tf32(kv.y);
            kv.z = to_tf32(kv.z); kv.w = to_tf32(kv.w);
            *(float4*)&sKP[row * 64 + ((lc ^ (row & 7)) << 2)] = kv;

            float4 vv = vreg[i];
            #pragma unroll
            for (int c = 0; c < 4; c++) {
                int dh = lc * 4 + c;
                float val = (c == 0) ? vv.x : (c == 1) ? vv.y : (c == 2) ? vv.z : vv.w;
                int f = (dh + (dh >> 3)) & 7;
                sVt[dh * 64 + (((row >> 2) ^ f) << 2) + (row & 3)] = to_tf32(val);
            }
        }
        __syncthreads();   // (B) K/V resident

        // ---- prefetch next tile into registers (overlaps with compute) ----
        if (kt < qt) {
            const float* Kn = Kg + (size_t)(kt + 1) * 64 * 64;
            const float* Vn = Vg + (size_t)(kt + 1) * 64 * 64;
            #pragma unroll
            for (int i = 0; i < 4; i++) {
                int row = lr + i * 16;
                kreg[i] = *(const float4*)&Kn[(size_t)row * 64 + lc * 4];
                vreg[i] = *(const float4*)&Vn[(size_t)row * 64 + lc * 4];
            }
        }

        // ---- S = Q K^T : warp tile 16 x 32 ----
        float sacc[4][4];
        #pragma unroll
        for (int nt = 0; nt < 4; nt++)
            #pragma unroll
            for (int c = 0; c < 4; c++) sacc[nt][c] = 0.f;

        #pragma unroll
        for (int ks = 0; ks < 8; ks++) {
            uint32_t af[4];
            {
                int row = wm * 16 + r8 + (q & 1) * 8;
                int ch  = ks * 2 + (q >> 1);
                ldmx4(af, sQa + (uint32_t)(row * 256 + ((ch ^ (row & 7)) << 4)));
            }
            uint32_t bf[2][4];
            #pragma unroll
            for (int bp = 0; bp < 2; bp++) {
                int row = wn * 32 + bp * 16 + r8 + (q >> 1) * 8;
                int ch  = ks * 2 + (q & 1);
                ldmx4(bf[bp], sKPa + (uint32_t)(row * 256 + ((ch ^ (row & 7)) << 4)));
            }
            #pragma unroll
            for (int nt = 0; nt < 4; nt++)
                mma_tf32(sacc[nt], af,
                         bf[nt >> 1][(nt & 1) * 2], bf[nt >> 1][(nt & 1) * 2 + 1]);
        }
        __syncthreads();   // (C) all K ldmatrix reads done

        // ---- write scaled/masked S into sKP ----
        const float scale = 0.03125f;   // 1/sqrt(1024)
        const bool diag = (kt == qt);
        #pragma unroll
        for (int nt = 0; nt < 4; nt++) {
            #pragma unroll
            for (int r = 0; r < 2; r++) {
                int row = wm * 16 + g + r * 8;
                int col = wn * 32 + nt * 8 + t * 2;
                float v0 = sacc[nt][r * 2]     * scale;
                float v1 = sacc[nt][r * 2 + 1] * scale;
                if (diag) {
                    if (col     > row) v0 = -INFINITY;
                    if (col + 1 > row) v1 = -INFINITY;
                }
                *(float2*)&sKP[row * 64 + (((col >> 2) ^ (row & 7)) << 2) + (col & 3)] =
                    make_float2(v0, v1);
            }
        }
        __syncthreads();   // (D) S fully written

        // ---- full-row read: 8 float4 = half a row per lane ----
        float4 rv[8];
        #pragma unroll
        for (int i = 0; i < 8; i++) {
            int ch2 = (lane & 1) * 8 + i;
            rv[i] = *(const float4*)&sKP[rrow * 64 + ((ch2 ^ (rrow & 7)) << 2)];
        }
        float tmax = -INFINITY;
        #pragma unroll
        for (int i = 0; i < 8; i++)
            tmax = fmaxf(tmax, fmaxf(fmaxf(rv[i].x, rv[i].y), fmaxf(rv[i].z, rv[i].w)));
        tmax = fmaxf(tmax, __shfl_xor_sync(0xffffffffu, tmax, 1));

        float mo0 = __shfl_sync(0xffffffffu, m_i[0], rsrcA);
        float mo1 = __shfl_sync(0xffffffffu, m_i[1], rsrcA);
        float m_old_rr = ((lane >> 1) < 8) ? mo0 : mo1;
        float mnew_rr  = fmaxf(m_old_rr, tmax);

        __syncthreads();   // (E) all reads done; safe to overwrite with P

        float rsum = 0.f;
        #pragma unroll
        for (int i = 0; i < 8; i++) {
            rv[i].x = __expf(rv[i].x - mnew_rr);
            rv[i].y = __expf(rv[i].y - mnew_rr);
            rv[i].z = __expf(rv[i].z - mnew_rr);
            rv[i].w = __expf(rv[i].w - mnew_rr);
            rsum += rv[i].x + rv[i].y + rv[i].z + rv[i].w;
        }
        rsum += __shfl_xor_sync(0xffffffffu, rsum, 1);
        if ((lane & 1) == wn) {
            #pragma unroll
            for (int i = 0; i < 8; i++) {
                int ch2 = (lane & 1) * 8 + i;
                float4 pv = make_float4(to_tf32(rv[i].x), to_tf32(rv[i].y),
                                        to_tf32(rv[i].z), to_tf32(rv[i].w));
                *(float4*)&sKP[rrow * 64 + ((ch2 ^ (rrow & 7)) << 2)] = pv;
            }
        }

        // ---- update online stats in MMA layout; rescale ctx ----
        #pragma unroll
        for (int r = 0; r < 2; r++) {
            int src = (r == 0) ? mmaA : mmaB;
            float tm = __shfl_sync(0xffffffffu, tmax, src);
            float rs = __shfl_sync(0xffffffffu, rsum, src);
            float mn = fmaxf(m_i[r], tm);
            float alpha = __expf(m_i[r] - mn);
            m_i[r] = mn;
            l_i[r] = l_i[r] * alpha + rs;
            #pragma unroll
            for (int nt = 0; nt < 4; nt++) {
                ctx[nt][r * 2]     *= alpha;
                ctx[nt][r * 2 + 1] *= alpha;
            }
        }
        __syncthreads();   // (F) P fully written

        // ---- ctx += P V : A = P rows, B = Vt[dh][key] (new swizzle) ----
        #pragma unroll
        for (int ks = 0; ks < 8; ks++) {
            uint32_t pf[4];
            {
                int row = wm * 16 + r8 + (q & 1) * 8;
                int ch  = ks * 2 + (q >> 1);
                ldmx4(pf, sKPa + (uint32_t)(row * 256 + ((ch ^ (row & 7)) << 4)));
            }
            uint32_t bf[2][4];
            #pragma unroll
            for (int bp = 0; bp < 2; bp++) {
                int row = wn * 32 + bp * 16 + r8 + (q >> 1) * 8;   // dh
                int ch  = ks * 2 + (q & 1);                        // key chunk
                int f   = (row + (row >> 3)) & 7;
                ldmx4(bf[bp], sVa + (uint32_t)(row * 256 + ((ch ^ f) << 4)));
            }
            #pragma unroll
            for (int nt = 0; nt < 4; nt++)
                mma_tf32(ctx[nt], pf,
                         bf[nt >> 1][(nt & 1) * 2], bf[nt >> 1][(nt & 1) * 2 + 1]);
        }
    }

    // ---- normalize + write ctx [b*S+s][h*64+dh] (RNA-rounded) ----
    const int b = bh >> 4;
    const int h = bh & 15;
    #pragma unroll
    for (int r = 0; r < 2; r++) {
        float inv = 1.f / l_i[r];
        int srow  = qbase + wm * 16 + g + r * 8;
        float* dst = &g_ctx[((size_t)b * SS + srow) * DD + h * DHH];
        #pragma unroll
        for (int nt = 0; nt < 4; nt++) {
            int col = wn * 32 + nt * 8 + t * 2;
            float2 v = make_float2(to_tf32(ctx[nt][r * 2] * inv),
                                   to_tf32(ctx[nt][r * 2 + 1] * inv));
            *(float2*)&dst[col] = v;
        }
    }
}

// ---------------------------------------------------------------------------
extern "C" void kernel_launch(void* const* d_in, const int* in_sizes, int n_in,
                              void* d_out, int out_size)
{
    (void)in_sizes; (void)n_in; (void)out_size;
    const float* X  = (const float*)d_in[0];
    const float* Wq = (const float*)d_in[1];
    const float* Wk = (const float*)d_in[2];
    const float* Wv = (const float*)d_in[3];
    const float* Wo = (const float*)d_in[4];
    const float* bo = (const float*)d_in[5];
    float*       Y  = (float*)d_out;

    const int DYN_SMEM = 3 * (int)STAGE_BYTES + 1024;   // 99328
    cudaFuncSetAttribute(qkv_mma, cudaFuncAttributeMaxDynamicSharedMemorySize, DYN_SMEM);
    cudaFuncSetAttribute(out_mma, cudaFuncAttributeMaxDynamicSharedMemorySize, DYN_SMEM);

    dim3 gt(32, 32, 4);
    transpose_w<<<gt, dim3(32, 8)>>>(Wq, Wk, Wv, Wo);

    dim3 gqkv(DD / 128, MM / 128, 3);
    qkv_mma<<<gqkv, 256, DYN_SMEM>>>(X);

    dim3 gattn(SS / 64, BB * HH);
    attn_tc<<<gattn, 256>>>();

    dim3 go(DD / 128, MM / 128);
    out_mma<<<go, 256, DYN_SMEM>>>(bo, Y);
}

// round 12
// speedup vs baseline: 3.7008x; 1.3999x over previous
#include <cuda_runtime.h>
#include <math.h>
#include <stdint.h>

// Problem constants
#define BB   4
#define SS   2048
#define DD   1024
#define HH   16
#define DHH  64
#define MM   (BB*SS)          // 8192 rows

// Scratch (static device globals -- EXACT round-5 set, no additions)
__device__ float g_Q[BB*HH*SS*DHH];     // [b*H+h][s][dh]
__device__ float g_K[BB*HH*SS*DHH];
__device__ float g_V[BB*HH*SS*DHH];
__device__ float g_ctx[MM*DD];          // [b*S+s][H*dh]
__device__ float g_Wt[4u*1024u*1024u];  // W^T for q,k,v,o : [n][k], tf32-rounded

// ---------------------------------------------------------------------------
// PTX helpers (baseline sm_100: mma.sync / ldmatrix / cp.async only)
// ---------------------------------------------------------------------------
__device__ __forceinline__ uint32_t smem_u32(const void* p) {
    uint32_t a;
    asm("{ .reg .u64 t; cvta.to.shared.u64 t, %1; cvt.u32.u64 %0, t; }" : "=r"(a) : "l"(p));
    return a;
}

__device__ __forceinline__ float to_tf32(float x) {
    uint32_t u;
    asm("cvt.rna.tf32.f32 %0, %1;" : "=r"(u) : "f"(x));
    return __uint_as_float(u);
}

__device__ __forceinline__ uint32_t to_tf32_u(float x) {
    uint32_t u;
    asm("cvt.rna.tf32.f32 %0, %1;" : "=r"(u) : "f"(x));
    return u;
}

#define CP_ASYNC16(sa, ga) asm volatile("cp.async.cg.shared.global [%0], [%1], 16;" :: "r"(sa), "l"(ga))
#define CP_COMMIT()        asm volatile("cp.async.commit_group;" ::: "memory")
#define CP_WAIT2()         asm volatile("cp.async.wait_group 2;" ::: "memory")
#define CP_WAIT0()         asm volatile("cp.async.wait_group 0;" ::: "memory")

__device__ __forceinline__ void ldmx4(uint32_t r[4], uint32_t addr) {
    asm volatile("ldmatrix.sync.aligned.m8n8.x4.shared.b16 {%0,%1,%2,%3}, [%4];"
        : "=r"(r[0]), "=r"(r[1]), "=r"(r[2]), "=r"(r[3]) : "r"(addr));
}

__device__ __forceinline__ void mma_tf32(float d[4], const uint32_t a[4],
                                         uint32_t b0, uint32_t b1) {
    asm volatile(
        "mma.sync.aligned.m16n8k8.row.col.f32.tf32.tf32.f32 "
        "{%0,%1,%2,%3}, {%4,%5,%6,%7}, {%8,%9}, {%0,%1,%2,%3};"
        : "+f"(d[0]), "+f"(d[1]), "+f"(d[2]), "+f"(d[3])
        : "r"(a[0]), "r"(a[1]), "r"(a[2]), "r"(a[3]), "r"(b0), "r"(b1));
}

// ---------------------------------------------------------------------------
// W transpose + tf32 rounding: g_Wt[z][n][k] = tf32(W_z[k][n])  [round-5 exact]
// ---------------------------------------------------------------------------
__global__ void transpose_w(const float* __restrict__ W0, const float* __restrict__ W1,
                            const float* __restrict__ W2, const float* __restrict__ W3)
{
    __shared__ float t[32][33];
    const float* W = (blockIdx.z == 0) ? W0 : (blockIdx.z == 1) ? W1 :
                     (blockIdx.z == 2) ? W2 : W3;
    float* O = g_Wt + (size_t)blockIdx.z * 1048576u;
    int tx = threadIdx.x, ty = threadIdx.y;
    int x  = blockIdx.x * 32 + tx;
    int y0 = blockIdx.y * 32;
    #pragma unroll
    for (int j = ty; j < 32; j += 8)
        t[j][tx] = W[(size_t)(y0 + j) * 1024 + x];
    __syncthreads();
    int nx  = blockIdx.y * 32 + tx;
    int ny0 = blockIdx.x * 32;
    #pragma unroll
    for (int j = ty; j < 32; j += 8)
        O[(size_t)(ny0 + j) * 1024 + nx] = to_tf32(t[tx][j]);
}

// ---------------------------------------------------------------------------
// tf32 mma.sync mainloop  [round-5 exact]
// ---------------------------------------------------------------------------
#define STAGE_BYTES 32768u   // A 16KB + B 16KB

__device__ __forceinline__ void mma_mainloop(const float* __restrict__ A,
                                             const float* __restrict__ Bt,
                                             uint32_t sb, float acc[4][4][4])
{
    const int tid  = threadIdx.x;
    const int lane = tid & 31;
    const int wid  = tid >> 5;
    const int wm   = wid >> 2;
    const int wn   = wid & 3;
    const int blockRow = blockIdx.y * 128;
    const int blockCol = blockIdx.x * 128;

    const int crow = tid >> 3;
    const int cchk = tid & 7;
    const int r8 = lane & 7;
    const int q  = lane >> 3;

    #pragma unroll
    for (int s = 0; s < 2; s++) {
        uint32_t as = sb + (uint32_t)s * STAGE_BYTES;
        uint32_t bs = as + 16384u;
        #pragma unroll
        for (int i = 0; i < 4; i++) {
            int row = crow + i * 32;
            uint32_t sw = (uint32_t)row * 128u + (uint32_t)((cchk ^ (row & 7)) << 4);
            CP_ASYNC16(as + sw, &A [(size_t)(blockRow + row) * 1024 + s * 32 + cchk * 4]);
            CP_ASYNC16(bs + sw, &Bt[(size_t)(blockCol + row) * 1024 + s * 32 + cchk * 4]);
        }
        CP_COMMIT();
    }

    for (int kc = 0; kc < 32; kc++) {
        int nk = kc + 2;
        if (nk < 32) {
            int st = nk % 3;
            uint32_t as = sb + (uint32_t)st * STAGE_BYTES;
            uint32_t bs = as + 16384u;
            #pragma unroll
            for (int i = 0; i < 4; i++) {
                int row = crow + i * 32;
                uint32_t sw = (uint32_t)row * 128u + (uint32_t)((cchk ^ (row & 7)) << 4);
                CP_ASYNC16(as + sw, &A [(size_t)(blockRow + row) * 1024 + nk * 32 + cchk * 4]);
                CP_ASYNC16(bs + sw, &Bt[(size_t)(blockCol + row) * 1024 + nk * 32 + cchk * 4]);
            }
        }
        CP_COMMIT();
        CP_WAIT2();
        __syncthreads();

        uint32_t as = sb + (uint32_t)(kc % 3) * STAGE_BYTES;
        uint32_t bs = as + 16384u;

        #pragma unroll
        for (int ks = 0; ks < 4; ks++) {
            uint32_t af[4][4];
            #pragma unroll
            for (int mt = 0; mt < 4; mt++) {
                int row = wm * 64 + mt * 16 + r8 + (q & 1) * 8;
                int ch  = ks * 2 + (q >> 1);
                ldmx4(af[mt], as + (uint32_t)row * 128u + (uint32_t)((ch ^ (row & 7)) << 4));
            }
            uint32_t bf[2][4];
            #pragma unroll
            for (int bp = 0; bp < 2; bp++) {
                int row = wn * 32 + bp * 16 + r8 + (q >> 1) * 8;
                int ch  = ks * 2 + (q & 1);
                ldmx4(bf[bp], bs + (uint32_t)row * 128u + (uint32_t)((ch ^ (row & 7)) << 4));
            }
            #pragma unroll
            for (int mt = 0; mt < 4; mt++)
                #pragma unroll
                for (int nt = 0; nt < 4; nt++)
                    mma_tf32(acc[mt][nt], af[mt],
                             bf[nt >> 1][(nt & 1) * 2], bf[nt >> 1][(nt & 1) * 2 + 1]);
        }
        __syncthreads();
    }
    CP_WAIT0();
}

// ---------------------------------------------------------------------------
// QKV projection: grid (8, 64, 3)  [round-5 exact]
// ---------------------------------------------------------------------------
__global__ __launch_bounds__(256, 2) void qkv_mma(const float* __restrict__ X)
{
    extern __shared__ char dsm[];
    uint32_t sraw = smem_u32(dsm);
    uint32_t sb   = (sraw + 1023u) & ~1023u;

    float acc[4][4][4];
    #pragma unroll
    for (int a = 0; a < 4; a++)
        #pragma unroll
        for (int bq = 0; bq < 4; bq++)
            #pragma unroll
            for (int c = 0; c < 4; c++) acc[a][bq][c] = 0.f;

    const float* Bt  = g_Wt + (size_t)blockIdx.z * 1048576u;
    float*       Out = (blockIdx.z == 0) ? g_Q : (blockIdx.z == 1) ? g_K : g_V;

    mma_mainloop(X, Bt, sb, acc);

    const int lane = threadIdx.x & 31;
    const int wid  = threadIdx.x >> 5;
    const int wm   = wid >> 2, wn = wid & 3;
    const int blockRow = blockIdx.y * 128;
    const int blockCol = blockIdx.x * 128;

    #pragma unroll
    for (int mt = 0; mt < 4; mt++) {
        int m0 = blockRow + wm * 64 + mt * 16 + (lane >> 2);
        #pragma unroll
        for (int half = 0; half < 2; half++) {
            int m = m0 + half * 8;
            int b = m >> 11, s = m & 2047;
            #pragma unroll
            for (int nt = 0; nt < 4; nt++) {
                int n = blockCol + wn * 32 + nt * 8 + (lane & 3) * 2;
                int h = n >> 6, d = n & 63;
                float2 v = make_float2(acc[mt][nt][half * 2], acc[mt][nt][half * 2 + 1]);
                *(float2*)&Out[((size_t)(b * HH + h) * SS + s) * DHH + d] = v;
            }
        }
    }
}

// ---------------------------------------------------------------------------
// Output projection: Y = g_ctx @ Wo + bo.  grid (8, 64)  [round-5 exact]
// ---------------------------------------------------------------------------
__global__ __launch_bounds__(256, 2) void out_mma(const float* __restrict__ bo,
                                                  float* __restrict__ Y)
{
    extern __shared__ char dsm[];
    uint32_t sraw = smem_u32(dsm);
    uint32_t sb   = (sraw + 1023u) & ~1023u;

    float acc[4][4][4];
    #pragma unroll
    for (int a = 0; a < 4; a++)
        #pragma unroll
        for (int bq = 0; bq < 4; bq++)
            #pragma unroll
            for (int c = 0; c < 4; c++) acc[a][bq][c] = 0.f;

    mma_mainloop(g_ctx, g_Wt + 3u * 1048576u, sb, acc);

    const int lane = threadIdx.x & 31;
    const int wid  = threadIdx.x >> 5;
    const int wm   = wid >> 2, wn = wid & 3;
    const int blockRow = blockIdx.y * 128;
    const int blockCol = blockIdx.x * 128;

    #pragma unroll
    for (int mt = 0; mt < 4; mt++) {
        int m0 = blockRow + wm * 64 + mt * 16 + (lane >> 2);
        #pragma unroll
        for (int half = 0; half < 2; half++) {
            int m = m0 + half * 8;
            #pragma unroll
            for (int nt = 0; nt < 4; nt++) {
                int n = blockCol + wn * 32 + nt * 8 + (lane & 3) * 2;
                float2 bv = *(const float2*)&bo[n];
                float2 v  = make_float2(acc[mt][nt][half * 2] + bv.x,
                                        acc[mt][nt][half * 2 + 1] + bv.y);
                *(float2*)&Y[(size_t)m * DD + n] = v;
            }
        }
    }
}

// ---------------------------------------------------------------------------
// Tensor-core causal flash attention — warp-local softmax, shuffle-P.
// grid (32 q-tiles, 64 bh), 128 threads (4 warps), Br=64, Bc=64.
// Warp w owns q-rows [w*16, w*16+16) x ALL 64 keys -> softmax rows are
// warp-local (2 shfls); P redistributed from softmax C-frags into PV A-frags
// via shuffles (no smem round-trip). 2 barriers per k-tile.
// Static smem 48KB: sQ[64x64] | sK[64x64] | sVt[64x64] (f(dh) swizzle).
// ---------------------------------------------------------------------------
__global__ __launch_bounds__(128) void attn_tc()
{
    __shared__ float sQ[4096];
    __shared__ float sK[4096];
    __shared__ float sVt[4096];

    const int tid  = threadIdx.x;        // 128 threads
    const int lane = tid & 31;
    const int w    = tid >> 5;           // 0..3
    const int r8   = lane & 7;
    const int q    = lane >> 3;
    const int g    = lane >> 2;          // acc row group
    const int t    = lane & 3;           // acc col pair
    const int bh   = blockIdx.y;
    const int qt   = (gridDim.x - 1) - blockIdx.x;   // heavy tiles first
    const int qbase = qt * 64;

    const float* Qg = g_Q + ((size_t)bh * SS + qbase) * DHH;
    const float* Kg = g_K + (size_t)bh * SS * DHH;
    const float* Vg = g_V + (size_t)bh * SS * DHH;

    const int lr = tid >> 4;   // 0..7 (+8 per iter)
    const int lc = tid & 15;

    const uint32_t sQa = smem_u32(sQ);
    const uint32_t sKa = smem_u32(sK);
    const uint32_t sVa = smem_u32(sVt);

    // ---- stage Q tile (RNA-rounded, swizzled) ----
    #pragma unroll
    for (int i = 0; i < 8; i++) {
        int row = lr + i * 8;
        float4 v = *(const float4*)&Qg[(size_t)row * 64 + lc * 4];
        v.x = to_tf32(v.x); v.y = to_tf32(v.y);
        v.z = to_tf32(v.z); v.w = to_tf32(v.w);
        *(float4*)&sQ[row * 64 + ((lc ^ (row & 7)) << 2)] = v;
    }

    float ctx[8][4];
    #pragma unroll
    for (int nt = 0; nt < 8; nt++)
        #pragma unroll
        for (int c = 0; c < 4; c++) ctx[nt][c] = 0.f;
    float m_i[2] = {-INFINITY, -INFINITY};
    float l_i[2] = {0.f, 0.f};

    for (int kt = 0; kt <= qt; kt++) {
        __syncthreads();   // (A) previous tile fully consumed

        // ---- load K (natural) and V (transposed, f(dh) swizzle), rounded ----
        const float* Kt = Kg + (size_t)kt * 64 * 64;
        const float* Vt = Vg + (size_t)kt * 64 * 64;
        #pragma unroll
        for (int i = 0; i < 8; i++) {
            int row = lr + i * 8;   // key
            float4 kv = *(const float4*)&Kt[(size_t)row * 64 + lc * 4];
            kv.x = to_tf32(kv.x); kv.y = to_tf32(kv.y);
            kv.z = to_tf32(kv.z); kv.w = to_tf32(kv.w);
            *(float4*)&sK[row * 64 + ((lc ^ (row & 7)) << 2)] = kv;

            float4 vv = *(const float4*)&Vt[(size_t)row * 64 + lc * 4];
            #pragma unroll
            for (int c = 0; c < 4; c++) {
                int dh = lc * 4 + c;
                float val = (c == 0) ? vv.x : (c == 1) ? vv.y : (c == 2) ? vv.z : vv.w;
                int f = (dh + (dh >> 3)) & 7;
                sVt[dh * 64 + (((row >> 2) ^ f) << 2) + (row & 3)] = to_tf32(val);
            }
        }
        __syncthreads();   // (B) K/V resident

        // ---- S = Q K^T  (warp tile 16 q x 64 keys) ----
        float sacc[8][4];
        #pragma unroll
        for (int nt = 0; nt < 8; nt++)
            #pragma unroll
            for (int c = 0; c < 4; c++) sacc[nt][c] = 0.f;

        #pragma unroll
        for (int ks = 0; ks < 8; ks++) {
            uint32_t af[4];
            {
                int row = w * 16 + r8 + (q & 1) * 8;
                int ch  = ks * 2 + (q >> 1);
                ldmx4(af, sQa + (uint32_t)(row * 256 + ((ch ^ (row & 7)) << 4)));
            }
            uint32_t bf[4][4];
            #pragma unroll
            for (int bp = 0; bp < 4; bp++) {
                int row = bp * 16 + r8 + (q >> 1) * 8;   // key
                int ch  = ks * 2 + (q & 1);
                ldmx4(bf[bp], sKa + (uint32_t)(row * 256 + ((ch ^ (row & 7)) << 4)));
            }
            #pragma unroll
            for (int nt = 0; nt < 8; nt++)
                mma_tf32(sacc[nt], af,
                         bf[nt >> 1][(nt & 1) * 2], bf[nt >> 1][(nt & 1) * 2 + 1]);
        }

        // ---- online softmax (p written back into sacc) ----
        const float scale = 0.03125f;   // 1/sqrt(1024)
        const bool masked = (kt == qt);
        #pragma unroll
        for (int r = 0; r < 2; r++) {
            int qrow = qbase + w * 16 + g + r * 8;
            float mx = -INFINITY;
            #pragma unroll
            for (int nt = 0; nt < 8; nt++) {
                float v0 = sacc[nt][r * 2]     * scale;
                float v1 = sacc[nt][r * 2 + 1] * scale;
                if (masked) {
                    int key = kt * 64 + nt * 8 + t * 2;
                    if (key     > qrow) v0 = -INFINITY;
                    if (key + 1 > qrow) v1 = -INFINITY;
                }
                sacc[nt][r * 2]     = v0;
                sacc[nt][r * 2 + 1] = v1;
                mx = fmaxf(mx, fmaxf(v0, v1));
            }
            mx = fmaxf(mx, __shfl_xor_sync(0xffffffffu, mx, 1));
            mx = fmaxf(mx, __shfl_xor_sync(0xffffffffu, mx, 2));
            float mn    = fmaxf(m_i[r], mx);
            float alpha = __expf(m_i[r] - mn);
            m_i[r] = mn;
            float rs = 0.f;
            #pragma unroll
            for (int nt = 0; nt < 8; nt++) {
                float p0 = __expf(sacc[nt][r * 2]     - mn);
                float p1 = __expf(sacc[nt][r * 2 + 1] - mn);
                sacc[nt][r * 2]     = p0;
                sacc[nt][r * 2 + 1] = p1;
                rs += p0 + p1;
                ctx[nt][r * 2]     *= alpha;
                ctx[nt][r * 2 + 1] *= alpha;
            }
            rs += __shfl_xor_sync(0xffffffffu, rs, 1);
            rs += __shfl_xor_sync(0xffffffffu, rs, 2);
            l_i[r] = l_i[r] * alpha + rs;
        }

        // ---- ctx += P V : A-frags built from sacc via shuffles ----
        // a0 = P[g][kcol], a1 = P[g+8][kcol], a2 = P[g][kcol+4], a3 = P[g+8][kcol+4]
        // owner of col j: lane g*4 + (j>>1) mod-pair, component parity (j&1)
        const int srcA = (g << 2) + (t >> 1);
        const int srcB = srcA + 2;
        const bool odd = (t & 1);
        #pragma unroll
        for (int ks = 0; ks < 8; ks++) {
            float e0 = __shfl_sync(0xffffffffu, sacc[ks][0], srcA);
            float e1 = __shfl_sync(0xffffffffu, sacc[ks][1], srcA);
            float e2 = __shfl_sync(0xffffffffu, sacc[ks][2], srcA);
            float e3 = __shfl_sync(0xffffffffu, sacc[ks][3], srcA);
            float f0 = __shfl_sync(0xffffffffu, sacc[ks][0], srcB);
            float f1 = __shfl_sync(0xffffffffu, sacc[ks][1], srcB);
            float f2 = __shfl_sync(0xffffffffu, sacc[ks][2], srcB);
            float f3 = __shfl_sync(0xffffffffu, sacc[ks][3], srcB);
            uint32_t pa[4];
            pa[0] = to_tf32_u(odd ? e1 : e0);
            pa[1] = to_tf32_u(odd ? e3 : e2);
            pa[2] = to_tf32_u(odd ? f1 : f0);
            pa[3] = to_tf32_u(odd ? f3 : f2);

            uint32_t bf[4][4];
            #pragma unroll
            for (int bp = 0; bp < 4; bp++) {
                int row = bp * 16 + r8 + (q >> 1) * 8;   // dh
                int ch  = ks * 2 + (q & 1);              // key chunk
                int f   = (row + (row >> 3)) & 7;
                ldmx4(bf[bp], sVa + (uint32_t)(row * 256 + ((ch ^ f) << 4)));
            }
            #pragma unroll
            for (int nt = 0; nt < 8; nt++)
                mma_tf32(ctx[nt], pa,
                         bf[nt >> 1][(nt & 1) * 2], bf[nt >> 1][(nt & 1) * 2 + 1]);
        }
    }

    // ---- normalize + write ctx [b*S+s][h*64+dh] (RNA-rounded) ----
    const int b = bh >> 4;
    const int h = bh & 15;
    #pragma unroll
    for (int r = 0; r < 2; r++) {
        float inv = 1.f / l_i[r];
        int srow  = qbase + w * 16 + g + r * 8;
        float* dst = &g_ctx[((size_t)b * SS + srow) * DD + h * DHH];
        #pragma unroll
        for (int nt = 0; nt < 8; nt++) {
            float2 v = make_float2(to_tf32(ctx[nt][r * 2] * inv),
                                   to_tf32(ctx[nt][r * 2 + 1] * inv));
            *(float2*)&dst[nt * 8 + t * 2] = v;
        }
    }
}

// ---------------------------------------------------------------------------
extern "C" void kernel_launch(void* const* d_in, const int* in_sizes, int n_in,
                              void* d_out, int out_size)
{
    (void)in_sizes; (void)n_in; (void)out_size;
    const float* X  = (const float*)d_in[0];
    const float* Wq = (const float*)d_in[1];
    const float* Wk = (const float*)d_in[2];
    const float* Wv = (const float*)d_in[3];
    const float* Wo = (const float*)d_in[4];
    const float* bo = (const float*)d_in[5];
    float*       Y  = (float*)d_out;

    const int DYN_SMEM = 3 * (int)STAGE_BYTES + 1024;   // 99328
    cudaFuncSetAttribute(qkv_mma, cudaFuncAttributeMaxDynamicSharedMemorySize, DYN_SMEM);
    cudaFuncSetAttribute(out_mma, cudaFuncAttributeMaxDynamicSharedMemorySize, DYN_SMEM);

    dim3 gt(32, 32, 4);
    transpose_w<<<gt, dim3(32, 8)>>>(Wq, Wk, Wv, Wo);

    dim3 gqkv(DD / 128, MM / 128, 3);
    qkv_mma<<<gqkv, 256, DYN_SMEM>>>(X);

    dim3 gattn(SS / 64, BB * HH);
    attn_tc<<<gattn, 128>>>();

    dim3 go(DD / 128, MM / 128);
    out_mma<<<go, 256, DYN_SMEM>>>(bo, Y);
}